// round 4
// baseline (speedup 1.0000x reference)
#include <cuda_runtime.h>
#include <math.h>

// Problem constants
#define T_  2
#define B_  16
#define C_  256
#define N_  4096
#define NH_ 8
#define D_  32

constexpr int TSTR = B_ * C_ * N_;   // 16,777,216 elements per timestep slab
constexpr int SZ   = T_ * TSTR;      // 33,554,432 elements per tensor

// Scratch (device globals: no allocation allowed)
__device__ float g_s[SZ];                       // attn spikes [T,B,C,N]
__device__ float g_kv[T_ * B_ * NH_ * D_ * D_]; // kv per (t,b,h): [32,32]

// ---------------------------------------------------------------------------
// Kernel 1: LIF on raw input x -> xs (binary spikes), bit-exact vs reference.
// v = v + (x - v)/2 ; s = (v >= 1) ; hard reset.
// ---------------------------------------------------------------------------
__global__ __launch_bounds__(256) void lif_x_kernel(const float4* __restrict__ x,
                                                    float4* __restrict__ xs) {
    int idx = blockIdx.x * 256 + threadIdx.x;      // over TSTR/4
    float4 a0 = x[idx];
    float4 a1 = x[idx + TSTR / 4];
    float4 r0, r1;
    const float* p0 = (const float*)&a0;
    const float* p1 = (const float*)&a1;
    float* q0 = (float*)&r0;
    float* q1 = (float*)&r1;
#pragma unroll
    for (int i = 0; i < 4; i++) {
        float v = p0[i] * 0.5f;                    // 0 + (x0-0)/2
        float s0 = (v >= 1.0f) ? 1.0f : 0.0f;
        if (s0 != 0.0f) v = 0.0f;
        v = v + (p1[i] - v) * 0.5f;
        float s1 = (v >= 1.0f) ? 1.0f : 0.0f;
        q0[i] = s0;
        q1[i] = s1;
    }
    xs[idx] = r0;
    xs[idx + TSTR / 4] = r1;
}

// ---------------------------------------------------------------------------
// Kernel 2: fp32 GEMM (W[256,256] @ X[256,4096]) + BN + LIF over T=2.
// Both timesteps accumulated in the same thread so the LIF recurrence is local.
// Tile: 64(o) x 64(n), 256 threads, 4x4 micro-tile, K-chunks of 16.
// ---------------------------------------------------------------------------
__global__ __launch_bounds__(256) void gemm_bn_lif_kernel(
    const float* __restrict__ Wm, const float* __restrict__ xs,
    float* __restrict__ outp,
    const float* __restrict__ gamma, const float* __restrict__ beta,
    const float* __restrict__ mean, const float* __restrict__ var) {
    __shared__ float Ws[16][68];
    __shared__ float Xs[2][16][64];

    const int n0 = blockIdx.x * 64;
    const int o0 = blockIdx.y * 64;
    const int b  = blockIdx.z;
    const float* x0 = xs + (size_t)b * (C_ * N_);
    const float* x1 = xs + (size_t)(B_ + b) * (C_ * N_);

    const int tid = threadIdx.x;
    const int tx = tid & 15;   // n lane
    const int ty = tid >> 4;   // o lane

    float acc0[4][4], acc1[4][4];
#pragma unroll
    for (int i = 0; i < 4; i++)
#pragma unroll
        for (int j = 0; j < 4; j++) { acc0[i][j] = 0.f; acc1[i][j] = 0.f; }

    const int wo  = tid >> 2;        // 0..63
    const int wc4 = (tid & 3) << 2;  // 0,4,8,12
    const int xc  = tid >> 4;        // 0..15
    const int xn4 = (tid & 15) << 2; // 0..60

    for (int c0 = 0; c0 < C_; c0 += 16) {
        float4 wv  = *(const float4*)&Wm[(o0 + wo) * C_ + c0 + wc4];
        float4 xv0 = *(const float4*)&x0[(size_t)(c0 + xc) * N_ + n0 + xn4];
        float4 xv1 = *(const float4*)&x1[(size_t)(c0 + xc) * N_ + n0 + xn4];
        __syncthreads();
        Ws[wc4 + 0][wo] = wv.x;
        Ws[wc4 + 1][wo] = wv.y;
        Ws[wc4 + 2][wo] = wv.z;
        Ws[wc4 + 3][wo] = wv.w;
        *(float4*)&Xs[0][xc][xn4] = xv0;
        *(float4*)&Xs[1][xc][xn4] = xv1;
        __syncthreads();
#pragma unroll
        for (int kk = 0; kk < 16; kk++) {
            float4 av = *(const float4*)&Ws[kk][ty << 2];
            float4 b0 = *(const float4*)&Xs[0][kk][tx << 2];
            float4 b1 = *(const float4*)&Xs[1][kk][tx << 2];
            float a[4] = {av.x, av.y, av.z, av.w};
            float u[4] = {b0.x, b0.y, b0.z, b0.w};
            float w[4] = {b1.x, b1.y, b1.z, b1.w};
#pragma unroll
            for (int i = 0; i < 4; i++)
#pragma unroll
                for (int j = 0; j < 4; j++) {
                    acc0[i][j] += a[i] * u[j];
                    acc1[i][j] += a[i] * w[j];
                }
        }
    }

#pragma unroll
    for (int i = 0; i < 4; i++) {
        int o = o0 + (ty << 2) + i;
        float g  = gamma[o];
        float sq = sqrtf(var[o] + 1e-5f);
        float inv = g / sq;
        float sh  = beta[o] - mean[o] * g / sq;
        float s0v[4], s1v[4];
#pragma unroll
        for (int j = 0; j < 4; j++) {
            float y0 = acc0[i][j] * inv + sh;
            float y1 = acc1[i][j] * inv + sh;
            float v = y0 * 0.5f;
            float sp0 = (v >= 1.0f) ? 1.0f : 0.0f;
            if (sp0 != 0.0f) v = 0.0f;
            v = v + (y1 - v) * 0.5f;
            float sp1 = (v >= 1.0f) ? 1.0f : 0.0f;
            s0v[j] = sp0;
            s1v[j] = sp1;
        }
        size_t base0 = ((size_t)b * C_ + o) * N_ + n0 + (tx << 2);
        size_t base1 = ((size_t)(B_ + b) * C_ + o) * N_ + n0 + (tx << 2);
        *(float4*)&outp[base0] = make_float4(s0v[0], s0v[1], s0v[2], s0v[3]);
        *(float4*)&outp[base1] = make_float4(s1v[0], s1v[1], s1v[2], s1v[3]);
    }
}

// ---------------------------------------------------------------------------
// Kernel 3: kv[t,b,h,d,e] = sum_n k[.,n,d] * v[.,n,e]   (binary inputs -> exact)
// One block per (t,b,h); 256 threads; each thread owns 4 (d) x 1 (e) accums.
// ---------------------------------------------------------------------------
__global__ __launch_bounds__(256) void kv_kernel(const float* __restrict__ kq,
                                                 const float* __restrict__ vq) {
    int h = blockIdx.x, b = blockIdx.y, t = blockIdx.z;
    const float* kb = kq + ((size_t)(t * B_ + b) * C_ + h * D_) * N_;
    const float* vb = vq + ((size_t)(t * B_ + b) * C_ + h * D_) * N_;
    __shared__ float ks[64][33];
    __shared__ float vs[64][33];
    int tid = threadIdx.x;
    int e  = tid & 31;
    int d0 = (tid >> 5) << 2;
    float acc[4] = {0.f, 0.f, 0.f, 0.f};

    for (int n0 = 0; n0 < N_; n0 += 64) {
        __syncthreads();
        for (int l = tid; l < 2048; l += 256) {
            int d = l >> 6;
            int nn = l & 63;
            ks[nn][d] = kb[(size_t)d * N_ + n0 + nn];
            vs[nn][d] = vb[(size_t)d * N_ + n0 + nn];
        }
        __syncthreads();
#pragma unroll 4
        for (int i = 0; i < 64; i++) {
            float ve = vs[i][e];
#pragma unroll
            for (int j = 0; j < 4; j++) acc[j] += ks[i][d0 + j] * ve;
        }
    }
    float* kvout = g_kv + ((size_t)(t * B_ + b) * NH_ + h) * (D_ * D_);
#pragma unroll
    for (int j = 0; j < 4; j++) kvout[(d0 + j) * D_ + e] = acc[j];
}

// ---------------------------------------------------------------------------
// Kernel 4: attn = q @ kv * 0.125 (exact integers), then LIF(th=0.5) -> g_s.
// Block per (n-tile of 128, h, b). q staged in smem; s transposed in smem for
// coalesced global writes.
// ---------------------------------------------------------------------------
__global__ __launch_bounds__(256) void attn_kernel(const float* __restrict__ qq) {
    __shared__ float kvs[2][32][32];   // 8 KB
    __shared__ float qs[2][128][33];   // 33 KB (reused as s-staging)
    int n0 = blockIdx.x * 128;
    int h = blockIdx.y;
    int b = blockIdx.z;
    int tid = threadIdx.x;

    for (int l = tid; l < 2048; l += 256) {
        int t = l >> 10;
        int de = l & 1023;
        kvs[t][de >> 5][de & 31] =
            g_kv[((size_t)(t * B_ + b) * NH_ + h) * 1024 + de];
    }
    for (int l = tid; l < 2048; l += 256) {
        int t = l >> 10;
        int r = l & 1023;
        int d = r >> 5;
        int nn4 = r & 31;
        float4 qv = *(const float4*)&qq[((size_t)(t * B_ + b) * C_ + h * D_ + d) * N_ +
                                        n0 + (nn4 << 2)];
        qs[t][(nn4 << 2) + 0][d] = qv.x;
        qs[t][(nn4 << 2) + 1][d] = qv.y;
        qs[t][(nn4 << 2) + 2][d] = qv.z;
        qs[t][(nn4 << 2) + 3][d] = qv.w;
    }
    __syncthreads();

    int e = tid & 31;
    int nlb = tid >> 5;
    float sp0[16], sp1[16];
#pragma unroll
    for (int r = 0; r < 16; r++) {
        int nl = (nlb << 4) + r;
        float a0 = 0.f, a1 = 0.f;
#pragma unroll
        for (int d = 0; d < 32; d++) {
            a0 += qs[0][nl][d] * kvs[0][d][e];
            a1 += qs[1][nl][d] * kvs[1][d][e];
        }
        a0 *= 0.125f;
        a1 *= 0.125f;
        float v = a0 * 0.5f;
        float t0 = (v >= 0.5f) ? 1.0f : 0.0f;
        if (t0 != 0.0f) v = 0.0f;
        v = v + (a1 - v) * 0.5f;
        float t1 = (v >= 0.5f) ? 1.0f : 0.0f;
        sp0[r] = t0;
        sp1[r] = t1;
    }
    __syncthreads();
    // Re-stage as ss[t][e][nl] (stride 132 -> 16B-aligned float4, 4-way conflicts)
    float* ss = &qs[0][0][0];  // capacity 8448 floats; need 2*32*132 = 8448
#pragma unroll
    for (int r = 0; r < 16; r++) {
        int nl = (nlb << 4) + r;
        ss[(0 * 32 + e) * 132 + nl] = sp0[r];
        ss[(1 * 32 + e) * 132 + nl] = sp1[r];
    }
    __syncthreads();
    for (int l = tid; l < 2048; l += 256) {
        int t = l >> 10;
        int r = l & 1023;
        int ee = r >> 5;
        int nn4 = r & 31;
        float4 sv = *(const float4*)&ss[((t << 5) + ee) * 132 + (nn4 << 2)];
        *(float4*)&g_s[((size_t)(t * B_ + b) * C_ + h * D_ + ee) * N_ + n0 +
                       (nn4 << 2)] = sv;
    }
}

// ---------------------------------------------------------------------------
// Kernel 5: out = BN(wp @ s + bp). Timesteps independent -> z covers t*B+b.
// ---------------------------------------------------------------------------
__global__ __launch_bounds__(256) void gemm_bn_bias_kernel(
    const float* __restrict__ Wm, float* __restrict__ outp,
    const float* __restrict__ bp,
    const float* __restrict__ gamma, const float* __restrict__ beta,
    const float* __restrict__ mean, const float* __restrict__ var) {
    __shared__ float Ws[16][68];
    __shared__ float Xs[16][64];

    const int n0 = blockIdx.x * 64;
    const int o0 = blockIdx.y * 64;
    const int z  = blockIdx.z;  // t*B + b, 0..31
    const float* x0 = g_s + (size_t)z * (C_ * N_);

    const int tid = threadIdx.x;
    const int tx = tid & 15;
    const int ty = tid >> 4;

    float acc[4][4];
#pragma unroll
    for (int i = 0; i < 4; i++)
#pragma unroll
        for (int j = 0; j < 4; j++) acc[i][j] = 0.f;

    const int wo  = tid >> 2;
    const int wc4 = (tid & 3) << 2;
    const int xc  = tid >> 4;
    const int xn4 = (tid & 15) << 2;

    for (int c0 = 0; c0 < C_; c0 += 16) {
        float4 wv  = *(const float4*)&Wm[(o0 + wo) * C_ + c0 + wc4];
        float4 xv0 = *(const float4*)&x0[(size_t)(c0 + xc) * N_ + n0 + xn4];
        __syncthreads();
        Ws[wc4 + 0][wo] = wv.x;
        Ws[wc4 + 1][wo] = wv.y;
        Ws[wc4 + 2][wo] = wv.z;
        Ws[wc4 + 3][wo] = wv.w;
        *(float4*)&Xs[xc][xn4] = xv0;
        __syncthreads();
#pragma unroll
        for (int kk = 0; kk < 16; kk++) {
            float4 av = *(const float4*)&Ws[kk][ty << 2];
            float4 b0 = *(const float4*)&Xs[kk][tx << 2];
            float a[4] = {av.x, av.y, av.z, av.w};
            float u[4] = {b0.x, b0.y, b0.z, b0.w};
#pragma unroll
            for (int i = 0; i < 4; i++)
#pragma unroll
                for (int j = 0; j < 4; j++) acc[i][j] += a[i] * u[j];
        }
    }

#pragma unroll
    for (int i = 0; i < 4; i++) {
        int o = o0 + (ty << 2) + i;
        float g  = gamma[o];
        float sq = sqrtf(var[o] + 1e-5f);
        float inv = g / sq;
        float sh  = beta[o] - mean[o] * g / sq;
        float bb  = bp[o];
        float rv[4];
#pragma unroll
        for (int j = 0; j < 4; j++) {
            float y = acc[i][j] + bb;
            rv[j] = y * inv + sh;
        }
        size_t base = ((size_t)z * C_ + o) * N_ + n0 + (tx << 2);
        *(float4*)&outp[base] = make_float4(rv[0], rv[1], rv[2], rv[3]);
    }
}

// ---------------------------------------------------------------------------
extern "C" void kernel_launch(void* const* d_in, const int* in_sizes, int n_in,
                              void* d_out, int out_size) {
    const float* x  = (const float*)d_in[0];
    const float* wq = (const float*)d_in[1];
    const float* wk = (const float*)d_in[2];
    const float* wv = (const float*)d_in[3];
    const float* wp = (const float*)d_in[4];
    const float* bp = (const float*)d_in[5];
    const float* qg = (const float*)d_in[6];
    const float* qb = (const float*)d_in[7];
    const float* qm = (const float*)d_in[8];
    const float* qv = (const float*)d_in[9];
    const float* kg = (const float*)d_in[10];
    const float* kb = (const float*)d_in[11];
    const float* km = (const float*)d_in[12];
    const float* kv_ = (const float*)d_in[13];
    const float* vg = (const float*)d_in[14];
    const float* vb = (const float*)d_in[15];
    const float* vm = (const float*)d_in[16];
    const float* vv = (const float*)d_in[17];
    const float* pg = (const float*)d_in[18];
    const float* pb = (const float*)d_in[19];
    const float* pm = (const float*)d_in[20];
    const float* pv = (const float*)d_in[21];

    float* out = (float*)d_out;
    float* xs = out + (size_t)SZ;       // output #2
    float* qo = out + 2 * (size_t)SZ;   // output #3
    float* ko = out + 3 * (size_t)SZ;   // output #4
    float* vo = out + 4 * (size_t)SZ;   // output #5

    // 1) input LIF -> xs
    lif_x_kernel<<<TSTR / 4 / 256, 256>>>((const float4*)x, (float4*)xs);

    // 2) q/k/v GEMM + BN + LIF
    dim3 gg(N_ / 64, C_ / 64, B_);
    gemm_bn_lif_kernel<<<gg, 256>>>(wq, xs, qo, qg, qb, qm, qv);
    gemm_bn_lif_kernel<<<gg, 256>>>(wk, xs, ko, kg, kb, km, kv_);
    gemm_bn_lif_kernel<<<gg, 256>>>(wv, xs, vo, vg, vb, vm, vv);

    // 3) kv = k^T v per (t,b,h)
    kv_kernel<<<dim3(NH_, B_, T_), 256>>>(ko, vo);

    // 4) attn + LIF(0.5) -> g_s
    attn_kernel<<<dim3(N_ / 128, NH_, B_), 256>>>(qo);

    // 5) projection GEMM + bias + BN -> out
    gemm_bn_bias_kernel<<<dim3(N_ / 64, C_ / 64, T_ * B_), 256>>>(
        wp, out, bp, pg, pb, pm, pv);
}

// round 6
// speedup vs baseline: 2.1034x; 2.1034x over previous
#include <cuda_runtime.h>
#include <cuda_bf16.h>
#include <math.h>
#include <stdint.h>

// Problem constants
#define T_  2
#define B_  16
#define C_  256
#define N_  4096
#define NH_ 8
#define D_  32

constexpr int TSTR = B_ * C_ * N_;   // elements per timestep slab
constexpr int SZ   = T_ * TSTR;      // elements per tensor

// ---------------------------------------------------------------------------
// Scratch (device globals; uint4-typed for 16B alignment)
// ---------------------------------------------------------------------------
__device__ uint4 g_xt4[SZ / 8];              // bf16 xs transposed [t,b][n][c]
__device__ uint4 g_st4[SZ / 8];              // bf16 attn spikes transposed [t,b][n][c]
__device__ uint4 g_whi4[4 * 65536 / 8];      // bf16 W_hi for {q,k,v,p}
__device__ uint4 g_wlo4[4 * 65536 / 8];      // bf16 W_lo
__device__ float g_kv[T_ * B_ * NH_ * D_ * D_];

// ---------------------------------------------------------------------------
// PTX helpers (arch-agnostic: ldmatrix / mma.sync / cp.async)
// ---------------------------------------------------------------------------
__device__ __forceinline__ uint32_t smem_u32(const void* p) {
    uint32_t a;
    asm("{ .reg .u64 t; cvta.to.shared.u64 t, %1; cvt.u32.u64 %0, t; }"
        : "=r"(a) : "l"(p));
    return a;
}
__device__ __forceinline__ void cp16(uint32_t dst, const void* src) {
    asm volatile("cp.async.ca.shared.global [%0], [%1], 16;" :: "r"(dst), "l"(src));
}
#define CP_COMMIT() asm volatile("cp.async.commit_group;" ::: "memory")
#define CP_WAIT1()  asm volatile("cp.async.wait_group 1;" ::: "memory")
#define CP_WAIT0()  asm volatile("cp.async.wait_group 0;" ::: "memory")

__device__ __forceinline__ void ldm4(uint32_t* r, uint32_t addr) {
    asm volatile("ldmatrix.sync.aligned.m8n8.x4.shared.b16 {%0,%1,%2,%3}, [%4];"
                 : "=r"(r[0]), "=r"(r[1]), "=r"(r[2]), "=r"(r[3]) : "r"(addr));
}
__device__ __forceinline__ void mma16816(float* d, const uint32_t* a, const uint32_t* b) {
    asm volatile(
        "mma.sync.aligned.m16n8k16.row.col.f32.bf16.bf16.f32 "
        "{%0,%1,%2,%3}, {%4,%5,%6,%7}, {%8,%9}, {%0,%1,%2,%3};"
        : "+f"(d[0]), "+f"(d[1]), "+f"(d[2]), "+f"(d[3])
        : "r"(a[0]), "r"(a[1]), "r"(a[2]), "r"(a[3]), "r"(b[0]), "r"(b[1]));
}

// Stage layout (bytes), rows padded to 80B (32 bf16 data + 16B pad)
constexpr uint32_t WH_OFF = 0;        // 64 rows * 80
constexpr uint32_t WL_OFF = 5120;     // 64 rows * 80
constexpr uint32_t X0_OFF = 10240;    // 128 rows * 80
constexpr uint32_t X1_OFF = 20480;    // 128 rows * 80
constexpr uint32_t SSTG   = 30720;    // qkv stage size
constexpr uint32_t SSTG_P = 20480;    // p stage size (WH, WL, X)

// ---------------------------------------------------------------------------
// Kernel 0: split weights into bf16 hi + lo
// ---------------------------------------------------------------------------
__global__ __launch_bounds__(256) void split_w_kernel(const float* __restrict__ wq,
                                                      const float* __restrict__ wk,
                                                      const float* __restrict__ wv,
                                                      const float* __restrict__ wp) {
    int idx = blockIdx.x * 256 + threadIdx.x;   // 0..262143
    int m = idx >> 16;
    int i = idx & 65535;
    const float* src = (m == 0) ? wq : (m == 1) ? wk : (m == 2) ? wv : wp;
    float w = src[i];
    __nv_bfloat16 hi = __float2bfloat16(w);
    float lo = w - __bfloat162float(hi);
    ((__nv_bfloat16*)g_whi4)[idx] = hi;
    ((__nv_bfloat16*)g_wlo4)[idx] = __float2bfloat16(lo);
}

// ---------------------------------------------------------------------------
// Kernel 1: LIF on raw input x -> xs (fp32 output) + g_xt (bf16 transposed [n,c])
// ---------------------------------------------------------------------------
__global__ __launch_bounds__(256) void lif_x_t_kernel(const float* __restrict__ x,
                                                      float* __restrict__ xs) {
    __shared__ __align__(16) __nv_bfloat16 st[2][64][80];
    int n0 = blockIdx.x * 64, c0 = blockIdx.y * 64, b = blockIdx.z;
    int tid = threadIdx.x;
    int tx = tid & 15, ty = tid >> 4;
#pragma unroll
    for (int cc = 0; cc < 4; ++cc) {
        int c = c0 + cc * 16 + ty;
        size_t base0 = ((size_t)b * C_ + c) * N_ + n0 + tx * 4;
        size_t base1 = ((size_t)(B_ + b) * C_ + c) * N_ + n0 + tx * 4;
        float4 a0 = *(const float4*)&x[base0];
        float4 a1 = *(const float4*)&x[base1];
        float4 r0, r1;
        const float* p0 = (const float*)&a0;
        const float* p1 = (const float*)&a1;
        float* q0 = (float*)&r0;
        float* q1 = (float*)&r1;
#pragma unroll
        for (int i = 0; i < 4; i++) {
            float v = p0[i] * 0.5f;
            float s0 = (v >= 1.0f) ? 1.0f : 0.0f;
            if (s0 != 0.0f) v = 0.0f;
            v = v + (p1[i] - v) * 0.5f;
            float s1 = (v >= 1.0f) ? 1.0f : 0.0f;
            q0[i] = s0;
            q1[i] = s1;
        }
        *(float4*)&xs[base0] = r0;
        *(float4*)&xs[base1] = r1;
        int cl = cc * 16 + ty;
#pragma unroll
        for (int i = 0; i < 4; i++) {
            st[0][tx * 4 + i][cl] = __float2bfloat16(q0[i]);
            st[1][tx * 4 + i][cl] = __float2bfloat16(q1[i]);
        }
    }
    __syncthreads();
    __nv_bfloat16* xt = (__nv_bfloat16*)g_xt4;
#pragma unroll
    for (int t = 0; t < 2; ++t)
        for (int i = tid; i < 512; i += 256) {
            int nl = i >> 3, c8 = i & 7;
            uint4 v = *(const uint4*)&st[t][nl][c8 * 8];
            *(uint4*)&xt[((size_t)(t * B_ + b) * N_ + n0 + nl) * C_ + c0 + c8 * 8] = v;
        }
}

// ---------------------------------------------------------------------------
// Kernel 2: HMMA GEMM for q/k/v: D[o,n] = W[o,c] @ Xt[n,c]^T (split bf16, fp32
// accum), both timesteps in-register; epilogue BN + LIF -> fp32 spikes [c,n].
// Block: o=64, n=128. 8 warps = 2(o) x 4(n), warp tile 32x32 per timestep.
// ---------------------------------------------------------------------------
__global__ __launch_bounds__(256) void hmma_qkv(
    int widx, float* __restrict__ outp,
    const float* __restrict__ gamma, const float* __restrict__ beta,
    const float* __restrict__ mean, const float* __restrict__ var) {
    extern __shared__ __align__(16) char smem[];
    uint32_t sb = smem_u32(smem);
    const int tid = threadIdx.x;
    const int lane = tid & 31;
    const int wid = tid >> 5;
    const int wo = wid >> 2;
    const int wn = wid & 3;
    const int n0 = blockIdx.x * 128;
    const int o0 = blockIdx.y * 64;
    const int b  = blockIdx.z;

    const __nv_bfloat16* wh = (const __nv_bfloat16*)g_whi4 + widx * 65536 + o0 * C_;
    const __nv_bfloat16* wl = (const __nv_bfloat16*)g_wlo4 + widx * 65536 + o0 * C_;
    const __nv_bfloat16* xt = (const __nv_bfloat16*)g_xt4;
    const __nv_bfloat16* x0g = xt + ((size_t)b * N_ + n0) * C_;
    const __nv_bfloat16* x1g = xt + ((size_t)(B_ + b) * N_ + n0) * C_;

    float d[2][4][2][4];
#pragma unroll
    for (int a = 0; a < 2; a++)
#pragma unroll
        for (int c = 0; c < 4; c++)
#pragma unroll
            for (int t = 0; t < 2; t++)
#pragma unroll
                for (int j = 0; j < 4; j++) d[a][c][t][j] = 0.f;

    // per-thread load slots: it0 WH, it1 WL, it2/3 X0, it4/5 X1
    const int lr = tid >> 2;        // 0..63
    const int lj = tid & 3;         // 16B chunk
    auto load_chunk = [&](int c0, int stg) {
        uint32_t s0 = sb + (uint32_t)stg * SSTG;
        cp16(s0 + WH_OFF + lr * 80 + lj * 16, wh + (size_t)lr * C_ + c0 + lj * 8);
        cp16(s0 + WL_OFF + lr * 80 + lj * 16, wl + (size_t)lr * C_ + c0 + lj * 8);
        cp16(s0 + X0_OFF + lr * 80 + lj * 16, x0g + (size_t)lr * C_ + c0 + lj * 8);
        cp16(s0 + X0_OFF + (64 + lr) * 80 + lj * 16, x0g + (size_t)(64 + lr) * C_ + c0 + lj * 8);
        cp16(s0 + X1_OFF + lr * 80 + lj * 16, x1g + (size_t)lr * C_ + c0 + lj * 8);
        cp16(s0 + X1_OFF + (64 + lr) * 80 + lj * 16, x1g + (size_t)(64 + lr) * C_ + c0 + lj * 8);
    };

    load_chunk(0, 0);
    CP_COMMIT();

    const int arow = (lane & 7) + ((lane >> 3) & 1) * 8;   // A: row add
    const int acol = ((lane >> 4) & 1) * 16;               // A: k byte add
    const int brow = (lane & 7) + ((lane >> 4) & 1) * 8;   // B: row add
    const int bcol = ((lane >> 3) & 1) * 16;               // B: k byte add

    for (int ch = 0; ch < 8; ++ch) {
        if (ch < 7) {
            load_chunk((ch + 1) * 32, (ch + 1) & 1);
            CP_COMMIT();
            CP_WAIT1();
        } else {
            CP_WAIT0();
        }
        __syncthreads();
        uint32_t s0 = sb + (uint32_t)(ch & 1) * SSTG;
        uint32_t aW = s0 + WH_OFF + (wo * 32) * 80;
        uint32_t aX = s0 + X0_OFF + (wn * 32) * 80;
#pragma unroll
        for (int k16 = 0; k16 < 2; ++k16) {
            int kb = k16 * 32;
            uint32_t ah[2][4], al[2][4];
#pragma unroll
            for (int ot = 0; ot < 2; ++ot) {
                uint32_t ad = aW + (uint32_t)(ot * 16 + arow) * 80 + kb + acol;
                ldm4(ah[ot], ad);
                ldm4(al[ot], ad + (WL_OFF - WH_OFF));
            }
            uint32_t bf[2][4][2];
#pragma unroll
            for (int t = 0; t < 2; ++t) {
                uint32_t bbase = aX + (uint32_t)t * (X1_OFF - X0_OFF);
#pragma unroll
                for (int ns = 0; ns < 2; ++ns) {
                    uint32_t r[4];
                    ldm4(r, bbase + (uint32_t)(ns * 16 + brow) * 80 + kb + bcol);
                    bf[t][ns * 2][0] = r[0];
                    bf[t][ns * 2][1] = r[1];
                    bf[t][ns * 2 + 1][0] = r[2];
                    bf[t][ns * 2 + 1][1] = r[3];
                }
            }
#pragma unroll
            for (int t = 0; t < 2; ++t)
#pragma unroll
                for (int ot = 0; ot < 2; ++ot)
#pragma unroll
                    for (int nt = 0; nt < 4; ++nt) {
                        mma16816(d[ot][nt][t], ah[ot], bf[t][nt]);
                        mma16816(d[ot][nt][t], al[ot], bf[t][nt]);
                    }
        }
        __syncthreads();
    }

    // Epilogue: BN + LIF over both timesteps, write fp32 spikes [c, n]
    const int obase = o0 + wo * 32 + (lane >> 2);
    const int nbase = n0 + wn * 32 + 2 * (lane & 3);
#pragma unroll
    for (int ot = 0; ot < 2; ++ot) {
#pragma unroll
        for (int rr = 0; rr < 2; ++rr) {
            int o = obase + ot * 16 + rr * 8;
            float g  = __ldg(&gamma[o]);
            float sq = sqrtf(__ldg(&var[o]) + 1e-5f);
            float inv = g / sq;
            float sh  = __ldg(&beta[o]) - __ldg(&mean[o]) * g / sq;
            size_t ro0 = ((size_t)b * C_ + o) * N_;
            size_t ro1 = ((size_t)(B_ + b) * C_ + o) * N_;
#pragma unroll
            for (int nt = 0; nt < 4; ++nt) {
                int n = nbase + nt * 8;
                float s0v[2], s1v[2];
#pragma unroll
                for (int cc = 0; cc < 2; ++cc) {
                    float y0 = d[ot][nt][0][rr * 2 + cc] * inv + sh;
                    float y1 = d[ot][nt][1][rr * 2 + cc] * inv + sh;
                    float v = y0 * 0.5f;
                    float sp0 = (v >= 1.0f) ? 1.0f : 0.0f;
                    if (sp0 != 0.0f) v = 0.0f;
                    v = v + (y1 - v) * 0.5f;
                    float sp1 = (v >= 1.0f) ? 1.0f : 0.0f;
                    s0v[cc] = sp0;
                    s1v[cc] = sp1;
                }
                *(float2*)&outp[ro0 + n] = make_float2(s0v[0], s0v[1]);
                *(float2*)&outp[ro1 + n] = make_float2(s1v[0], s1v[1]);
            }
        }
    }
}

// ---------------------------------------------------------------------------
// Kernel 5: HMMA GEMM for projection: out[z,o,n] = BN(Wp @ s + bp).
// Same structure, single timestep per block (z = t*B+b).
// ---------------------------------------------------------------------------
__global__ __launch_bounds__(256) void hmma_p(
    float* __restrict__ outp, const float* __restrict__ bp,
    const float* __restrict__ gamma, const float* __restrict__ beta,
    const float* __restrict__ mean, const float* __restrict__ var) {
    extern __shared__ __align__(16) char smem[];
    uint32_t sb = smem_u32(smem);
    const int tid = threadIdx.x;
    const int lane = tid & 31;
    const int wid = tid >> 5;
    const int wo = wid >> 2;
    const int wn = wid & 3;
    const int n0 = blockIdx.x * 128;
    const int o0 = blockIdx.y * 64;
    const int z  = blockIdx.z;

    const __nv_bfloat16* wh = (const __nv_bfloat16*)g_whi4 + 3 * 65536 + o0 * C_;
    const __nv_bfloat16* wl = (const __nv_bfloat16*)g_wlo4 + 3 * 65536 + o0 * C_;
    const __nv_bfloat16* xg = (const __nv_bfloat16*)g_st4 + ((size_t)z * N_ + n0) * C_;

    float d[2][4][4];
#pragma unroll
    for (int a = 0; a < 2; a++)
#pragma unroll
        for (int c = 0; c < 4; c++)
#pragma unroll
            for (int j = 0; j < 4; j++) d[a][c][j] = 0.f;

    const int lr = tid >> 2;
    const int lj = tid & 3;
    auto load_chunk = [&](int c0, int stg) {
        uint32_t s0 = sb + (uint32_t)stg * SSTG_P;
        cp16(s0 + WH_OFF + lr * 80 + lj * 16, wh + (size_t)lr * C_ + c0 + lj * 8);
        cp16(s0 + WL_OFF + lr * 80 + lj * 16, wl + (size_t)lr * C_ + c0 + lj * 8);
        cp16(s0 + X0_OFF + lr * 80 + lj * 16, xg + (size_t)lr * C_ + c0 + lj * 8);
        cp16(s0 + X0_OFF + (64 + lr) * 80 + lj * 16, xg + (size_t)(64 + lr) * C_ + c0 + lj * 8);
    };

    load_chunk(0, 0);
    CP_COMMIT();

    const int arow = (lane & 7) + ((lane >> 3) & 1) * 8;
    const int acol = ((lane >> 4) & 1) * 16;
    const int brow = (lane & 7) + ((lane >> 4) & 1) * 8;
    const int bcol = ((lane >> 3) & 1) * 16;

    for (int ch = 0; ch < 8; ++ch) {
        if (ch < 7) {
            load_chunk((ch + 1) * 32, (ch + 1) & 1);
            CP_COMMIT();
            CP_WAIT1();
        } else {
            CP_WAIT0();
        }
        __syncthreads();
        uint32_t s0 = sb + (uint32_t)(ch & 1) * SSTG_P;
        uint32_t aW = s0 + WH_OFF + (wo * 32) * 80;
        uint32_t aX = s0 + X0_OFF + (wn * 32) * 80;
#pragma unroll
        for (int k16 = 0; k16 < 2; ++k16) {
            int kb = k16 * 32;
            uint32_t ah[2][4], al[2][4];
#pragma unroll
            for (int ot = 0; ot < 2; ++ot) {
                uint32_t ad = aW + (uint32_t)(ot * 16 + arow) * 80 + kb + acol;
                ldm4(ah[ot], ad);
                ldm4(al[ot], ad + (WL_OFF - WH_OFF));
            }
            uint32_t bf[4][2];
#pragma unroll
            for (int ns = 0; ns < 2; ++ns) {
                uint32_t r[4];
                ldm4(r, aX + (uint32_t)(ns * 16 + brow) * 80 + kb + bcol);
                bf[ns * 2][0] = r[0];
                bf[ns * 2][1] = r[1];
                bf[ns * 2 + 1][0] = r[2];
                bf[ns * 2 + 1][1] = r[3];
            }
#pragma unroll
            for (int ot = 0; ot < 2; ++ot)
#pragma unroll
                for (int nt = 0; nt < 4; ++nt) {
                    mma16816(d[ot][nt], ah[ot], bf[nt]);
                    mma16816(d[ot][nt], al[ot], bf[nt]);
                }
        }
        __syncthreads();
    }

    const int obase = o0 + wo * 32 + (lane >> 2);
    const int nbase = n0 + wn * 32 + 2 * (lane & 3);
#pragma unroll
    for (int ot = 0; ot < 2; ++ot) {
#pragma unroll
        for (int rr = 0; rr < 2; ++rr) {
            int o = obase + ot * 16 + rr * 8;
            float g  = __ldg(&gamma[o]);
            float sq = sqrtf(__ldg(&var[o]) + 1e-5f);
            float inv = g / sq;
            float sh  = __ldg(&beta[o]) - __ldg(&mean[o]) * g / sq;
            float bb  = __ldg(&bp[o]);
            size_t ro = ((size_t)z * C_ + o) * N_;
#pragma unroll
            for (int nt = 0; nt < 4; ++nt) {
                int n = nbase + nt * 8;
                float y0 = (d[ot][nt][rr * 2 + 0] + bb) * inv + sh;
                float y1 = (d[ot][nt][rr * 2 + 1] + bb) * inv + sh;
                *(float2*)&outp[ro + n] = make_float2(y0, y1);
            }
        }
    }
}

// ---------------------------------------------------------------------------
// Kernel 3: kv[t,b,h,d,e] = sum_n k[.,n,d] * v[.,n,e]  (binary -> exact)
// ---------------------------------------------------------------------------
__global__ __launch_bounds__(256) void kv_kernel(const float* __restrict__ kq,
                                                 const float* __restrict__ vq) {
    int h = blockIdx.x, b = blockIdx.y, t = blockIdx.z;
    const float* kb = kq + ((size_t)(t * B_ + b) * C_ + h * D_) * N_;
    const float* vb = vq + ((size_t)(t * B_ + b) * C_ + h * D_) * N_;
    __shared__ float ks[64][33];
    __shared__ float vs[64][33];
    int tid = threadIdx.x;
    int e  = tid & 31;
    int d0 = (tid >> 5) << 2;
    float acc[4] = {0.f, 0.f, 0.f, 0.f};

    for (int n0 = 0; n0 < N_; n0 += 64) {
        __syncthreads();
        for (int l = tid; l < 2048; l += 256) {
            int d = l >> 6;
            int nn = l & 63;
            ks[nn][d] = kb[(size_t)d * N_ + n0 + nn];
            vs[nn][d] = vb[(size_t)d * N_ + n0 + nn];
        }
        __syncthreads();
#pragma unroll 4
        for (int i = 0; i < 64; i++) {
            float ve = vs[i][e];
#pragma unroll
            for (int j = 0; j < 4; j++) acc[j] += ks[i][d0 + j] * ve;
        }
    }
    float* kvout = g_kv + ((size_t)(t * B_ + b) * NH_ + h) * (D_ * D_);
#pragma unroll
    for (int j = 0; j < 4; j++) kvout[(d0 + j) * D_ + e] = acc[j];
}

// ---------------------------------------------------------------------------
// Kernel 4: attn = q @ kv * 0.125 (exact), LIF(th=0.5) -> g_st (bf16 [n,c])
// ---------------------------------------------------------------------------
__global__ __launch_bounds__(256) void attn_kernel(const float* __restrict__ qq) {
    __shared__ float kvs[2][32][32];
    __shared__ float qs[2][128][33];
    int n0 = blockIdx.x * 128;
    int h = blockIdx.y;
    int b = blockIdx.z;
    int tid = threadIdx.x;

    for (int l = tid; l < 2048; l += 256) {
        int t = l >> 10;
        int de = l & 1023;
        kvs[t][de >> 5][de & 31] =
            g_kv[((size_t)(t * B_ + b) * NH_ + h) * 1024 + de];
    }
    for (int l = tid; l < 2048; l += 256) {
        int t = l >> 10;
        int r = l & 1023;
        int d = r >> 5;
        int nn4 = r & 31;
        float4 qv = *(const float4*)&qq[((size_t)(t * B_ + b) * C_ + h * D_ + d) * N_ +
                                        n0 + (nn4 << 2)];
        qs[t][(nn4 << 2) + 0][d] = qv.x;
        qs[t][(nn4 << 2) + 1][d] = qv.y;
        qs[t][(nn4 << 2) + 2][d] = qv.z;
        qs[t][(nn4 << 2) + 3][d] = qv.w;
    }
    __syncthreads();

    __nv_bfloat16* stt = (__nv_bfloat16*)g_st4;
    int e = tid & 31;
    int nlb = tid >> 5;
#pragma unroll
    for (int r = 0; r < 16; r++) {
        int nl = (nlb << 4) + r;
        float a0 = 0.f, a1 = 0.f;
#pragma unroll
        for (int d = 0; d < 32; d++) {
            a0 += qs[0][nl][d] * kvs[0][d][e];
            a1 += qs[1][nl][d] * kvs[1][d][e];
        }
        a0 *= 0.125f;
        a1 *= 0.125f;
        float v = a0 * 0.5f;
        float t0 = (v >= 0.5f) ? 1.0f : 0.0f;
        if (t0 != 0.0f) v = 0.0f;
        v = v + (a1 - v) * 0.5f;
        float t1 = (v >= 0.5f) ? 1.0f : 0.0f;
        stt[((size_t)b * N_ + n0 + nl) * C_ + h * D_ + e] = __float2bfloat16(t0);
        stt[((size_t)(B_ + b) * N_ + n0 + nl) * C_ + h * D_ + e] = __float2bfloat16(t1);
    }
}

// ---------------------------------------------------------------------------
extern "C" void kernel_launch(void* const* d_in, const int* in_sizes, int n_in,
                              void* d_out, int out_size) {
    const float* x  = (const float*)d_in[0];
    const float* wq = (const float*)d_in[1];
    const float* wk = (const float*)d_in[2];
    const float* wv = (const float*)d_in[3];
    const float* wp = (const float*)d_in[4];
    const float* bp = (const float*)d_in[5];
    const float* qg = (const float*)d_in[6];
    const float* qb = (const float*)d_in[7];
    const float* qm = (const float*)d_in[8];
    const float* qv = (const float*)d_in[9];
    const float* kg = (const float*)d_in[10];
    const float* kb = (const float*)d_in[11];
    const float* km = (const float*)d_in[12];
    const float* kv_ = (const float*)d_in[13];
    const float* vg = (const float*)d_in[14];
    const float* vb = (const float*)d_in[15];
    const float* vm = (const float*)d_in[16];
    const float* vv = (const float*)d_in[17];
    const float* pg = (const float*)d_in[18];
    const float* pb = (const float*)d_in[19];
    const float* pm = (const float*)d_in[20];
    const float* pv = (const float*)d_in[21];

    float* out = (float*)d_out;
    float* xs = out + (size_t)SZ;
    float* qo = out + 2 * (size_t)SZ;
    float* ko = out + 3 * (size_t)SZ;
    float* vo = out + 4 * (size_t)SZ;

    cudaFuncSetAttribute(hmma_qkv, cudaFuncAttributeMaxDynamicSharedMemorySize, 2 * SSTG);
    cudaFuncSetAttribute(hmma_p, cudaFuncAttributeMaxDynamicSharedMemorySize, 2 * SSTG_P);

    // 0) weight split
    split_w_kernel<<<1024, 256>>>(wq, wk, wv, wp);

    // 1) input LIF -> xs (fp32) + transposed bf16 activations
    lif_x_t_kernel<<<dim3(N_ / 64, C_ / 64, B_), 256>>>(x, xs);

    // 2) q/k/v HMMA GEMM + BN + LIF
    dim3 gg(N_ / 128, C_ / 64, B_);
    hmma_qkv<<<gg, 256, 2 * SSTG>>>(0, qo, qg, qb, qm, qv);
    hmma_qkv<<<gg, 256, 2 * SSTG>>>(1, ko, kg, kb, km, kv_);
    hmma_qkv<<<gg, 256, 2 * SSTG>>>(2, vo, vg, vb, vm, vv);

    // 3) kv = k^T v per (t,b,h)
    kv_kernel<<<dim3(NH_, B_, T_), 256>>>(ko, vo);

    // 4) attn + LIF(0.5) -> transposed bf16 spikes
    attn_kernel<<<dim3(N_ / 128, NH_, B_), 256>>>(qo);

    // 5) projection HMMA GEMM + bias + BN -> out
    hmma_p<<<dim3(N_ / 128, C_ / 64, T_ * B_), 256, 2 * SSTG_P>>>(
        out, bp, pg, pb, pm, pv);
}

// round 9
// speedup vs baseline: 3.5889x; 1.7062x over previous
#include <cuda_runtime.h>
#include <cuda_bf16.h>
#include <math.h>
#include <stdint.h>

// Problem constants
#define T_  2
#define B_  16
#define C_  256
#define N_  4096
#define NH_ 8
#define D_  32

constexpr int TSTR = B_ * C_ * N_;
constexpr int SZ   = T_ * TSTR;

// ---------------------------------------------------------------------------
// Scratch (device globals)
// ---------------------------------------------------------------------------
__device__ uint4 g_xt4[SZ / 8];              // bf16 xs transposed [t,b][n][c]
__device__ uint4 g_st4[SZ / 8];              // bf16 attn spikes transposed [t,b][n][c]
__device__ uint4 g_whi4[4 * 65536 / 8];      // bf16 W_hi {q,k,v,p}
__device__ uint4 g_wlo4[4 * 65536 / 8];      // bf16 W_lo
__device__ float g_kv[T_ * B_ * NH_ * D_ * D_];
__device__ uint32_t g_qpk[32 * N_ * 8];      // q bits packed along channel: [tb][n][8]
__device__ uint32_t g_kpk[32 * C_ * 128];    // k bits packed along n: [tb][c][128]
__device__ uint32_t g_vpk[32 * C_ * 128];    // v bits packed along n: [tb][c][128]

// ---------------------------------------------------------------------------
// PTX helpers (arch-agnostic)
// ---------------------------------------------------------------------------
__device__ __forceinline__ uint32_t smem_u32(const void* p) {
    uint32_t a;
    asm("{ .reg .u64 t; cvta.to.shared.u64 t, %1; cvt.u32.u64 %0, t; }"
        : "=r"(a) : "l"(p));
    return a;
}
__device__ __forceinline__ void cp16(uint32_t dst, const void* src) {
    asm volatile("cp.async.ca.shared.global [%0], [%1], 16;" :: "r"(dst), "l"(src));
}
#define CP_COMMIT() asm volatile("cp.async.commit_group;" ::: "memory")
#define CP_WAIT1()  asm volatile("cp.async.wait_group 1;" ::: "memory")
#define CP_WAIT0()  asm volatile("cp.async.wait_group 0;" ::: "memory")

__device__ __forceinline__ void ldm4(uint32_t* r, uint32_t addr) {
    asm volatile("ldmatrix.sync.aligned.m8n8.x4.shared.b16 {%0,%1,%2,%3}, [%4];"
                 : "=r"(r[0]), "=r"(r[1]), "=r"(r[2]), "=r"(r[3]) : "r"(addr));
}
__device__ __forceinline__ void mma16816(float* d, const uint32_t* a, const uint32_t* b) {
    asm volatile(
        "mma.sync.aligned.m16n8k16.row.col.f32.bf16.bf16.f32 "
        "{%0,%1,%2,%3}, {%4,%5,%6,%7}, {%8,%9}, {%0,%1,%2,%3};"
        : "+f"(d[0]), "+f"(d[1]), "+f"(d[2]), "+f"(d[3])
        : "r"(a[0]), "r"(a[1]), "r"(a[2]), "r"(a[3]), "r"(b[0]), "r"(b[1]));
}

// Stage layout (bytes), rows padded to 80B (32 bf16 data + 16B pad)
constexpr uint32_t WH_OFF = 0;
constexpr uint32_t WL_OFF = 5120;
constexpr uint32_t X0_OFF = 10240;
constexpr uint32_t X1_OFF = 20480;
constexpr uint32_t SSTG   = 30720;
constexpr uint32_t SSTG_P = 20480;

// ---------------------------------------------------------------------------
// Kernel 0: split weights into bf16 hi + lo
// ---------------------------------------------------------------------------
__global__ __launch_bounds__(256) void split_w_kernel(const float* __restrict__ wq,
                                                      const float* __restrict__ wk,
                                                      const float* __restrict__ wv,
                                                      const float* __restrict__ wp) {
    int idx = blockIdx.x * 256 + threadIdx.x;
    int m = idx >> 16;
    int i = idx & 65535;
    const float* src = (m == 0) ? wq : (m == 1) ? wk : (m == 2) ? wv : wp;
    float w = src[i];
    __nv_bfloat16 hi = __float2bfloat16(w);
    float lo = w - __bfloat162float(hi);
    ((__nv_bfloat16*)g_whi4)[idx] = hi;
    ((__nv_bfloat16*)g_wlo4)[idx] = __float2bfloat16(lo);
}

// ---------------------------------------------------------------------------
// Kernel 1: input LIF -> xs (fp32 output) + g_xt (bf16 transposed [n,c])
// ---------------------------------------------------------------------------
__global__ __launch_bounds__(256) void lif_x_t_kernel(const float* __restrict__ x,
                                                      float* __restrict__ xs) {
    __shared__ __align__(16) __nv_bfloat16 st[2][64][80];
    int n0 = blockIdx.x * 64, c0 = blockIdx.y * 64, b = blockIdx.z;
    int tid = threadIdx.x;
    int tx = tid & 15, ty = tid >> 4;
#pragma unroll
    for (int cc = 0; cc < 4; ++cc) {
        int c = c0 + cc * 16 + ty;
        size_t base0 = ((size_t)b * C_ + c) * N_ + n0 + tx * 4;
        size_t base1 = ((size_t)(B_ + b) * C_ + c) * N_ + n0 + tx * 4;
        float4 a0 = *(const float4*)&x[base0];
        float4 a1 = *(const float4*)&x[base1];
        float4 r0, r1;
        const float* p0 = (const float*)&a0;
        const float* p1 = (const float*)&a1;
        float* q0 = (float*)&r0;
        float* q1 = (float*)&r1;
#pragma unroll
        for (int i = 0; i < 4; i++) {
            float v = p0[i] * 0.5f;
            float s0 = (v >= 1.0f) ? 1.0f : 0.0f;
            if (s0 != 0.0f) v = 0.0f;
            v = v + (p1[i] - v) * 0.5f;
            float s1 = (v >= 1.0f) ? 1.0f : 0.0f;
            q0[i] = s0;
            q1[i] = s1;
        }
        *(float4*)&xs[base0] = r0;
        *(float4*)&xs[base1] = r1;
        int cl = cc * 16 + ty;
#pragma unroll
        for (int i = 0; i < 4; i++) {
            st[0][tx * 4 + i][cl] = __float2bfloat16(q0[i]);
            st[1][tx * 4 + i][cl] = __float2bfloat16(q1[i]);
        }
    }
    __syncthreads();
    __nv_bfloat16* xt = (__nv_bfloat16*)g_xt4;
#pragma unroll
    for (int t = 0; t < 2; ++t)
        for (int i = tid; i < 512; i += 256) {
            int nl = i >> 3, c8 = i & 7;
            uint4 v = *(const uint4*)&st[t][nl][c8 * 8];
            *(uint4*)&xt[((size_t)(t * B_ + b) * N_ + n0 + nl) * C_ + c0 + c8 * 8] = v;
        }
}

// ---------------------------------------------------------------------------
// Kernel 2: HMMA GEMM for q/k/v + BN + LIF; fp32 spike outputs + bit-packed
// spikes. MODE 0: pack along channel (q). MODE 1: pack along n (k, v).
// ---------------------------------------------------------------------------
template <int MODE>
__global__ __launch_bounds__(256) void hmma_qkv(
    int widx, float* __restrict__ outp,
    const float* __restrict__ gamma, const float* __restrict__ beta,
    const float* __restrict__ mean, const float* __restrict__ var) {
    extern __shared__ __align__(16) char smem[];
    uint32_t sb = smem_u32(smem);
    const int tid = threadIdx.x;
    const int lane = tid & 31;
    const int wid = tid >> 5;
    const int wo = wid >> 2;
    const int wn = wid & 3;
    const int n0 = blockIdx.x * 128;
    const int o0 = blockIdx.y * 64;
    const int b  = blockIdx.z;

    const __nv_bfloat16* wh = (const __nv_bfloat16*)g_whi4 + widx * 65536 + o0 * C_;
    const __nv_bfloat16* wl = (const __nv_bfloat16*)g_wlo4 + widx * 65536 + o0 * C_;
    const __nv_bfloat16* xt = (const __nv_bfloat16*)g_xt4;
    const __nv_bfloat16* x0g = xt + ((size_t)b * N_ + n0) * C_;
    const __nv_bfloat16* x1g = xt + ((size_t)(B_ + b) * N_ + n0) * C_;

    float d[2][4][2][4];
#pragma unroll
    for (int a = 0; a < 2; a++)
#pragma unroll
        for (int c = 0; c < 4; c++)
#pragma unroll
            for (int t = 0; t < 2; t++)
#pragma unroll
                for (int j = 0; j < 4; j++) d[a][c][t][j] = 0.f;

    const int lr = tid >> 2;
    const int lj = tid & 3;
    auto load_chunk = [&](int c0, int stg) {
        uint32_t s0 = sb + (uint32_t)stg * SSTG;
        cp16(s0 + WH_OFF + lr * 80 + lj * 16, wh + (size_t)lr * C_ + c0 + lj * 8);
        cp16(s0 + WL_OFF + lr * 80 + lj * 16, wl + (size_t)lr * C_ + c0 + lj * 8);
        cp16(s0 + X0_OFF + lr * 80 + lj * 16, x0g + (size_t)lr * C_ + c0 + lj * 8);
        cp16(s0 + X0_OFF + (64 + lr) * 80 + lj * 16, x0g + (size_t)(64 + lr) * C_ + c0 + lj * 8);
        cp16(s0 + X1_OFF + lr * 80 + lj * 16, x1g + (size_t)lr * C_ + c0 + lj * 8);
        cp16(s0 + X1_OFF + (64 + lr) * 80 + lj * 16, x1g + (size_t)(64 + lr) * C_ + c0 + lj * 8);
    };

    load_chunk(0, 0);
    CP_COMMIT();

    const int arow = (lane & 7) + ((lane >> 3) & 1) * 8;
    const int acol = ((lane >> 4) & 1) * 16;
    const int brow = (lane & 7) + ((lane >> 4) & 1) * 8;
    const int bcol = ((lane >> 3) & 1) * 16;

    for (int ch = 0; ch < 8; ++ch) {
        if (ch < 7) {
            load_chunk((ch + 1) * 32, (ch + 1) & 1);
            CP_COMMIT();
            CP_WAIT1();
        } else {
            CP_WAIT0();
        }
        __syncthreads();
        uint32_t s0 = sb + (uint32_t)(ch & 1) * SSTG;
        uint32_t aW = s0 + WH_OFF + (wo * 32) * 80;
        uint32_t aX = s0 + X0_OFF + (wn * 32) * 80;
#pragma unroll
        for (int k16 = 0; k16 < 2; ++k16) {
            int kb = k16 * 32;
            uint32_t ah[2][4], al[2][4];
#pragma unroll
            for (int ot = 0; ot < 2; ++ot) {
                uint32_t ad = aW + (uint32_t)(ot * 16 + arow) * 80 + kb + acol;
                ldm4(ah[ot], ad);
                ldm4(al[ot], ad + (WL_OFF - WH_OFF));
            }
            uint32_t bf[2][4][2];
#pragma unroll
            for (int t = 0; t < 2; ++t) {
                uint32_t bbase = aX + (uint32_t)t * (X1_OFF - X0_OFF);
#pragma unroll
                for (int ns = 0; ns < 2; ++ns) {
                    uint32_t r[4];
                    ldm4(r, bbase + (uint32_t)(ns * 16 + brow) * 80 + kb + bcol);
                    bf[t][ns * 2][0] = r[0];
                    bf[t][ns * 2][1] = r[1];
                    bf[t][ns * 2 + 1][0] = r[2];
                    bf[t][ns * 2 + 1][1] = r[3];
                }
            }
#pragma unroll
            for (int t = 0; t < 2; ++t)
#pragma unroll
                for (int ot = 0; ot < 2; ++ot)
#pragma unroll
                    for (int nt = 0; nt < 4; ++nt) {
                        mma16816(d[ot][nt][t], ah[ot], bf[t][nt]);
                        mma16816(d[ot][nt][t], al[ot], bf[t][nt]);
                    }
        }
        __syncthreads();
    }

    // Epilogue: BN + LIF, fp32 spike stores + bit packing
    const int la = lane & 3;
    const int g  = lane >> 2;
    const int obase = o0 + wo * 32 + g;
    const int nbase = n0 + wn * 32 + 2 * la;

    uint32_t pk[2][2][2];   // MODE1: [t][ot][rr] bits over (nt, la, cc)
    uint32_t pc[2][4][2];   // MODE0: [t][nt][cc] bits over (g, rr, ot)
#pragma unroll
    for (int t = 0; t < 2; ++t) {
#pragma unroll
        for (int i = 0; i < 2; ++i)
#pragma unroll
            for (int j = 0; j < 2; ++j) pk[t][i][j] = 0u;
#pragma unroll
        for (int i = 0; i < 4; ++i)
#pragma unroll
            for (int j = 0; j < 2; ++j) pc[t][i][j] = 0u;
    }

#pragma unroll
    for (int ot = 0; ot < 2; ++ot) {
#pragma unroll
        for (int rr = 0; rr < 2; ++rr) {
            int o = obase + ot * 16 + rr * 8;
            float gm = __ldg(&gamma[o]);
            float sq = sqrtf(__ldg(&var[o]) + 1e-5f);
            float inv = gm / sq;
            float sh  = __ldg(&beta[o]) - __ldg(&mean[o]) * gm / sq;
            size_t ro0 = ((size_t)b * C_ + o) * N_;
            size_t ro1 = ((size_t)(B_ + b) * C_ + o) * N_;
#pragma unroll
            for (int nt = 0; nt < 4; ++nt) {
                int n = nbase + nt * 8;
                float s0v[2], s1v[2];
#pragma unroll
                for (int cc = 0; cc < 2; ++cc) {
                    float y0 = d[ot][nt][0][rr * 2 + cc] * inv + sh;
                    float y1 = d[ot][nt][1][rr * 2 + cc] * inv + sh;
                    float v = y0 * 0.5f;
                    float sp0 = (v >= 1.0f) ? 1.0f : 0.0f;
                    if (sp0 != 0.0f) v = 0.0f;
                    v = v + (y1 - v) * 0.5f;
                    float sp1 = (v >= 1.0f) ? 1.0f : 0.0f;
                    s0v[cc] = sp0;
                    s1v[cc] = sp1;
                    if (MODE == 0) {
                        uint32_t bit = 1u << (g + rr * 8 + ot * 16);
                        if (sp0 != 0.0f) pc[0][nt][cc] |= bit;
                        if (sp1 != 0.0f) pc[1][nt][cc] |= bit;
                    } else {
                        uint32_t bit = 1u << (nt * 8 + la * 2 + cc);
                        if (sp0 != 0.0f) pk[0][ot][rr] |= bit;
                        if (sp1 != 0.0f) pk[1][ot][rr] |= bit;
                    }
                }
                *(float2*)&outp[ro0 + n] = make_float2(s0v[0], s0v[1]);
                *(float2*)&outp[ro1 + n] = make_float2(s1v[0], s1v[1]);
            }
        }
    }

    if (MODE == 0) {
        // q: pack along channel -> g_qpk[tb][n][hword]
        const int hword = (o0 + wo * 32) >> 5;
#pragma unroll
        for (int t = 0; t < 2; ++t)
#pragma unroll
            for (int nt = 0; nt < 4; ++nt)
#pragma unroll
                for (int cc = 0; cc < 2; ++cc) {
                    uint32_t w = pc[t][nt][cc];
                    w |= __shfl_xor_sync(0xffffffffu, w, 4);
                    w |= __shfl_xor_sync(0xffffffffu, w, 8);
                    w |= __shfl_xor_sync(0xffffffffu, w, 16);
                    if (g == 0) {
                        int n = nbase + nt * 8 + cc;
                        g_qpk[((size_t)(t * B_ + b) * N_ + n) * 8 + hword] = w;
                    }
                }
    } else {
        // k/v: pack along n -> g_{k,v}pk[tb][c][nword]
        uint32_t* pko = (widx == 1) ? g_kpk : g_vpk;
        const int nw = (n0 + wn * 32) >> 5;
#pragma unroll
        for (int t = 0; t < 2; ++t)
#pragma unroll
            for (int ot = 0; ot < 2; ++ot)
#pragma unroll
                for (int rr = 0; rr < 2; ++rr) {
                    uint32_t w = pk[t][ot][rr];
                    w |= __shfl_xor_sync(0xffffffffu, w, 1);
                    w |= __shfl_xor_sync(0xffffffffu, w, 2);
                    if (la == 0) {
                        int o = obase + ot * 16 + rr * 8;
                        pko[((size_t)(t * B_ + b) * C_ + o) * 128 + nw] = w;
                    }
                }
    }
}

// ---------------------------------------------------------------------------
// Kernel 3: kv via popcount over packed bits: kv[d][e] = sum_w popc(k&v)
// ---------------------------------------------------------------------------
__global__ __launch_bounds__(256) void kv_pk_kernel() {
    int h = blockIdx.x, b = blockIdx.y, t = blockIdx.z;
    int tb = t * B_ + b;
    __shared__ uint32_t ks[32 * 129];
    __shared__ uint32_t vs[32 * 129];
    int tid = threadIdx.x;
    const uint32_t* kp = g_kpk + ((size_t)tb * C_ + h * D_) * 128;
    const uint32_t* vp = g_vpk + ((size_t)tb * C_ + h * D_) * 128;
    for (int i = tid; i < 4096; i += 256) {
        int dd = i >> 7, w = i & 127;
        ks[dd * 129 + w] = kp[i];
        vs[dd * 129 + w] = vp[i];
    }
    __syncthreads();
    float* kvout = g_kv + ((size_t)tb * NH_ + h) * (D_ * D_);
    for (int p = tid; p < 1024; p += 256) {
        int dd = p >> 5, e = p & 31;
        const uint32_t* kd = ks + dd * 129;
        const uint32_t* ve = vs + e * 129;
        int acc = 0;
#pragma unroll 8
        for (int w = 0; w < 128; ++w) acc += __popc(kd[w] & ve[w]);
        kvout[p] = (float)acc;
    }
}

// ---------------------------------------------------------------------------
// Kernel 4: attn[n][e] = 0.125 * sum_{d: q bit} kv[d][e]; LIF(0.5) -> bf16 [n,c]
// ---------------------------------------------------------------------------
__global__ __launch_bounds__(256) void attn_pk_kernel() {
    __shared__ float kvs[2][32][33];
    int n0 = blockIdx.x * 128;
    int h = blockIdx.y;
    int b = blockIdx.z;
    int tid = threadIdx.x;

    for (int l = tid; l < 2048; l += 256) {
        int t = l >> 10;
        int r = l & 1023;
        kvs[t][r >> 5][r & 31] = g_kv[((size_t)(t * B_ + b) * NH_ + h) * 1024 + r];
    }
    __syncthreads();

    int nl = tid >> 1;
    int eh = (tid & 1) * 16;
    int nn = n0 + nl;
    uint32_t qw0 = g_qpk[((size_t)b * N_ + nn) * 8 + h];
    uint32_t qw1 = g_qpk[((size_t)(B_ + b) * N_ + nn) * 8 + h];

    float a0[16], a1[16];
#pragma unroll
    for (int j = 0; j < 16; ++j) { a0[j] = 0.f; a1[j] = 0.f; }
#pragma unroll 4
    for (int dd = 0; dd < 32; ++dd) {
        if ((qw0 >> dd) & 1) {
#pragma unroll
            for (int j = 0; j < 16; ++j) a0[j] += kvs[0][dd][eh + j];
        }
        if ((qw1 >> dd) & 1) {
#pragma unroll
            for (int j = 0; j < 16; ++j) a1[j] += kvs[1][dd][eh + j];
        }
    }

    __nv_bfloat16 o0[16], o1[16];
#pragma unroll
    for (int j = 0; j < 16; ++j) {
        float y0 = a0[j] * 0.125f;
        float y1 = a1[j] * 0.125f;
        float v = y0 * 0.5f;
        float t0 = (v >= 0.5f) ? 1.0f : 0.0f;
        if (t0 != 0.0f) v = 0.0f;
        v = v + (y1 - v) * 0.5f;
        float t1 = (v >= 0.5f) ? 1.0f : 0.0f;
        o0[j] = __float2bfloat16(t0);
        o1[j] = __float2bfloat16(t1);
    }
    __nv_bfloat16* stt = (__nv_bfloat16*)g_st4;
    size_t b0 = ((size_t)b * N_ + nn) * C_ + h * D_ + eh;
    size_t b1 = ((size_t)(B_ + b) * N_ + nn) * C_ + h * D_ + eh;
    *(uint4*)&stt[b0] = *(uint4*)&o0[0];
    *(uint4*)&stt[b0 + 8] = *(uint4*)&o0[8];
    *(uint4*)&stt[b1] = *(uint4*)&o1[0];
    *(uint4*)&stt[b1 + 8] = *(uint4*)&o1[8];
}

// ---------------------------------------------------------------------------
// Kernel 5: HMMA projection GEMM: out = BN(Wp @ s + bp)
// ---------------------------------------------------------------------------
__global__ __launch_bounds__(256) void hmma_p(
    float* __restrict__ outp, const float* __restrict__ bp,
    const float* __restrict__ gamma, const float* __restrict__ beta,
    const float* __restrict__ mean, const float* __restrict__ var) {
    extern __shared__ __align__(16) char smem[];
    uint32_t sb = smem_u32(smem);
    const int tid = threadIdx.x;
    const int lane = tid & 31;
    const int wid = tid >> 5;
    const int wo = wid >> 2;
    const int wn = wid & 3;
    const int n0 = blockIdx.x * 128;
    const int o0 = blockIdx.y * 64;
    const int z  = blockIdx.z;

    const __nv_bfloat16* wh = (const __nv_bfloat16*)g_whi4 + 3 * 65536 + o0 * C_;
    const __nv_bfloat16* wl = (const __nv_bfloat16*)g_wlo4 + 3 * 65536 + o0 * C_;
    const __nv_bfloat16* xg = (const __nv_bfloat16*)g_st4 + ((size_t)z * N_ + n0) * C_;

    float d[2][4][4];
#pragma unroll
    for (int a = 0; a < 2; a++)
#pragma unroll
        for (int c = 0; c < 4; c++)
#pragma unroll
            for (int j = 0; j < 4; j++) d[a][c][j] = 0.f;

    const int lr = tid >> 2;
    const int lj = tid & 3;
    auto load_chunk = [&](int c0, int stg) {
        uint32_t s0 = sb + (uint32_t)stg * SSTG_P;
        cp16(s0 + WH_OFF + lr * 80 + lj * 16, wh + (size_t)lr * C_ + c0 + lj * 8);
        cp16(s0 + WL_OFF + lr * 80 + lj * 16, wl + (size_t)lr * C_ + c0 + lj * 8);
        cp16(s0 + X0_OFF + lr * 80 + lj * 16, xg + (size_t)lr * C_ + c0 + lj * 8);
        cp16(s0 + X0_OFF + (64 + lr) * 80 + lj * 16, xg + (size_t)(64 + lr) * C_ + c0 + lj * 8);
    };

    load_chunk(0, 0);
    CP_COMMIT();

    const int arow = (lane & 7) + ((lane >> 3) & 1) * 8;
    const int acol = ((lane >> 4) & 1) * 16;
    const int brow = (lane & 7) + ((lane >> 4) & 1) * 8;
    const int bcol = ((lane >> 3) & 1) * 16;

    for (int ch = 0; ch < 8; ++ch) {
        if (ch < 7) {
            load_chunk((ch + 1) * 32, (ch + 1) & 1);
            CP_COMMIT();
            CP_WAIT1();
        } else {
            CP_WAIT0();
        }
        __syncthreads();
        uint32_t s0 = sb + (uint32_t)(ch & 1) * SSTG_P;
        uint32_t aW = s0 + WH_OFF + (wo * 32) * 80;
        uint32_t aX = s0 + X0_OFF + (wn * 32) * 80;
#pragma unroll
        for (int k16 = 0; k16 < 2; ++k16) {
            int kb = k16 * 32;
            uint32_t ah[2][4], al[2][4];
#pragma unroll
            for (int ot = 0; ot < 2; ++ot) {
                uint32_t ad = aW + (uint32_t)(ot * 16 + arow) * 80 + kb + acol;
                ldm4(ah[ot], ad);
                ldm4(al[ot], ad + (WL_OFF - WH_OFF));
            }
            uint32_t bf[4][2];
#pragma unroll
            for (int ns = 0; ns < 2; ++ns) {
                uint32_t r[4];
                ldm4(r, aX + (uint32_t)(ns * 16 + brow) * 80 + kb + bcol);
                bf[ns * 2][0] = r[0];
                bf[ns * 2][1] = r[1];
                bf[ns * 2 + 1][0] = r[2];
                bf[ns * 2 + 1][1] = r[3];
            }
#pragma unroll
            for (int ot = 0; ot < 2; ++ot)
#pragma unroll
                for (int nt = 0; nt < 4; ++nt) {
                    mma16816(d[ot][nt], ah[ot], bf[nt]);
                    mma16816(d[ot][nt], al[ot], bf[nt]);
                }
        }
        __syncthreads();
    }

    const int obase = o0 + wo * 32 + (lane >> 2);
    const int nbase = n0 + wn * 32 + 2 * (lane & 3);
#pragma unroll
    for (int ot = 0; ot < 2; ++ot) {
#pragma unroll
        for (int rr = 0; rr < 2; ++rr) {
            int o = obase + ot * 16 + rr * 8;
            float g  = __ldg(&gamma[o]);
            float sq = sqrtf(__ldg(&var[o]) + 1e-5f);
            float inv = g / sq;
            float sh  = __ldg(&beta[o]) - __ldg(&mean[o]) * g / sq;
            float bb  = __ldg(&bp[o]);
            size_t ro = ((size_t)z * C_ + o) * N_;
#pragma unroll
            for (int nt = 0; nt < 4; ++nt) {
                int n = nbase + nt * 8;
                float y0 = (d[ot][nt][rr * 2 + 0] + bb) * inv + sh;
                float y1 = (d[ot][nt][rr * 2 + 1] + bb) * inv + sh;
                *(float2*)&outp[ro + n] = make_float2(y0, y1);
            }
        }
    }
}

// ---------------------------------------------------------------------------
extern "C" void kernel_launch(void* const* d_in, const int* in_sizes, int n_in,
                              void* d_out, int out_size) {
    const float* x  = (const float*)d_in[0];
    const float* wq = (const float*)d_in[1];
    const float* wk = (const float*)d_in[2];
    const float* wv = (const float*)d_in[3];
    const float* wp = (const float*)d_in[4];
    const float* bp = (const float*)d_in[5];
    const float* qg = (const float*)d_in[6];
    const float* qb = (const float*)d_in[7];
    const float* qm = (const float*)d_in[8];
    const float* qv = (const float*)d_in[9];
    const float* kg = (const float*)d_in[10];
    const float* kb = (const float*)d_in[11];
    const float* km = (const float*)d_in[12];
    const float* kv_ = (const float*)d_in[13];
    const float* vg = (const float*)d_in[14];
    const float* vb = (const float*)d_in[15];
    const float* vm = (const float*)d_in[16];
    const float* vv = (const float*)d_in[17];
    const float* pg = (const float*)d_in[18];
    const float* pb = (const float*)d_in[19];
    const float* pm = (const float*)d_in[20];
    const float* pv = (const float*)d_in[21];

    float* out = (float*)d_out;
    float* xs = out + (size_t)SZ;
    float* qo = out + 2 * (size_t)SZ;
    float* ko = out + 3 * (size_t)SZ;
    float* vo = out + 4 * (size_t)SZ;

    cudaFuncSetAttribute(hmma_qkv<0>, cudaFuncAttributeMaxDynamicSharedMemorySize, 2 * SSTG);
    cudaFuncSetAttribute(hmma_qkv<1>, cudaFuncAttributeMaxDynamicSharedMemorySize, 2 * SSTG);
    cudaFuncSetAttribute(hmma_p, cudaFuncAttributeMaxDynamicSharedMemorySize, 2 * SSTG_P);

    // 0) weight split
    split_w_kernel<<<1024, 256>>>(wq, wk, wv, wp);

    // 1) input LIF -> xs (fp32) + transposed bf16 activations
    lif_x_t_kernel<<<dim3(N_ / 64, C_ / 64, B_), 256>>>(x, xs);

    // 2) q/k/v HMMA GEMM + BN + LIF (+ bit packing)
    dim3 gg(N_ / 128, C_ / 64, B_);
    hmma_qkv<0><<<gg, 256, 2 * SSTG>>>(0, qo, qg, qb, qm, qv);
    hmma_qkv<1><<<gg, 256, 2 * SSTG>>>(1, ko, kg, kb, km, kv_);
    hmma_qkv<1><<<gg, 256, 2 * SSTG>>>(2, vo, vg, vb, vm, vv);

    // 3) kv via popcount
    kv_pk_kernel<<<dim3(NH_, B_, T_), 256>>>();

    // 4) attn via masked row-sum + LIF(0.5) -> bf16 spikes
    attn_pk_kernel<<<dim3(N_ / 128, NH_, B_), 256>>>();

    // 5) projection HMMA GEMM + bias + BN -> out
    hmma_p<<<dim3(N_ / 128, C_ / 64, T_ * B_), 256, 2 * SSTG_P>>>(
        out, bp, pg, pb, pm, pv);
}

// round 13
// speedup vs baseline: 3.8032x; 1.0597x over previous
#include <cuda_runtime.h>
#include <cuda_bf16.h>
#include <math.h>
#include <stdint.h>

// Problem constants
#define T_  2
#define B_  16
#define C_  256
#define N_  4096
#define NH_ 8
#define D_  32

constexpr int TSTR = B_ * C_ * N_;
constexpr int SZ   = T_ * TSTR;

// ---------------------------------------------------------------------------
// Scratch (device globals)
// ---------------------------------------------------------------------------
__device__ uint4 g_xt4[SZ / 8];              // bf16 xs transposed [t,b][n][c]
__device__ uint4 g_st4[SZ / 8];              // bf16 attn spikes transposed [t,b][n][c]
__device__ uint4 g_whi4[4 * 65536 / 8];      // bf16 W_hi {q,k,v,p}
__device__ uint4 g_wlo4[4 * 65536 / 8];      // bf16 W_lo
__device__ float g_kv[T_ * B_ * NH_ * D_ * D_];
__device__ uint32_t g_qpk[32 * N_ * 8];      // q bits packed along channel
__device__ uint32_t g_kpk[32 * C_ * 128];    // k bits packed along n
__device__ uint32_t g_vpk[32 * C_ * 128];    // v bits packed along n

// ---------------------------------------------------------------------------
// PTX helpers (arch-agnostic)
// ---------------------------------------------------------------------------
__device__ __forceinline__ uint32_t smem_u32(const void* p) {
    uint32_t a;
    asm("{ .reg .u64 t; cvta.to.shared.u64 t, %1; cvt.u32.u64 %0, t; }"
        : "=r"(a) : "l"(p));
    return a;
}
__device__ __forceinline__ void cp16(uint32_t dst, const void* src) {
    asm volatile("cp.async.ca.shared.global [%0], [%1], 16;" :: "r"(dst), "l"(src));
}
#define CP_COMMIT() asm volatile("cp.async.commit_group;" ::: "memory")
#define CP_WAIT1()  asm volatile("cp.async.wait_group 1;" ::: "memory")
#define CP_WAIT0()  asm volatile("cp.async.wait_group 0;" ::: "memory")

__device__ __forceinline__ void ldm4(uint32_t* r, uint32_t addr) {
    asm volatile("ldmatrix.sync.aligned.m8n8.x4.shared.b16 {%0,%1,%2,%3}, [%4];"
                 : "=r"(r[0]), "=r"(r[1]), "=r"(r[2]), "=r"(r[3]) : "r"(addr));
}
__device__ __forceinline__ void mma16816(float* d, const uint32_t* a, const uint32_t* b) {
    asm volatile(
        "mma.sync.aligned.m16n8k16.row.col.f32.bf16.bf16.f32 "
        "{%0,%1,%2,%3}, {%4,%5,%6,%7}, {%8,%9}, {%0,%1,%2,%3};"
        : "+f"(d[0]), "+f"(d[1]), "+f"(d[2]), "+f"(d[3])
        : "r"(a[0]), "r"(a[1]), "r"(a[2]), "r"(a[3]), "r"(b[0]), "r"(b[1]));
}

// Stage layout (bytes), rows padded to 80B (32 bf16 data + 16B pad)
constexpr uint32_t WH_OFF = 0;
constexpr uint32_t WL_OFF = 5120;
constexpr uint32_t X0_OFF = 10240;
constexpr uint32_t X1_OFF = 20480;
constexpr uint32_t SSTG   = 30720;    // qkv stage size
constexpr uint32_t SSTG_P = 20480;    // p stage size

// ---------------------------------------------------------------------------
// Kernel 0: split weights into bf16 hi + lo
// ---------------------------------------------------------------------------
__global__ __launch_bounds__(256) void split_w_kernel(const float* __restrict__ wq,
                                                      const float* __restrict__ wk,
                                                      const float* __restrict__ wv,
                                                      const float* __restrict__ wp) {
    int idx = blockIdx.x * 256 + threadIdx.x;
    int m = idx >> 16;
    int i = idx & 65535;
    const float* src = (m == 0) ? wq : (m == 1) ? wk : (m == 2) ? wv : wp;
    float w = src[i];
    __nv_bfloat16 hi = __float2bfloat16(w);
    float lo = w - __bfloat162float(hi);
    ((__nv_bfloat16*)g_whi4)[idx] = hi;
    ((__nv_bfloat16*)g_wlo4)[idx] = __float2bfloat16(lo);
}

// ---------------------------------------------------------------------------
// Kernel 1: input LIF -> xs (fp32 output) + g_xt (bf16 transposed [n,c]).
// Conflict-free transpose: smem staged [c][n] with XOR swizzle on 8-half units.
// ---------------------------------------------------------------------------
__global__ __launch_bounds__(256) void lif_x_t_kernel(const float* __restrict__ x,
                                                      float* __restrict__ xs) {
    __shared__ __align__(16) uint16_t st[2][64][72];   // [t][c][n(+pad)], swizzled
    int n0 = blockIdx.x * 64, c0 = blockIdx.y * 64, b = blockIdx.z;
    int tid = threadIdx.x;
    int tx = tid & 15, ty = tid >> 4;
#pragma unroll
    for (int cc = 0; cc < 4; ++cc) {
        int cl = cc * 16 + ty;
        int c = c0 + cl;
        size_t base0 = ((size_t)b * C_ + c) * N_ + n0 + tx * 4;
        size_t base1 = ((size_t)(B_ + b) * C_ + c) * N_ + n0 + tx * 4;
        float4 a0 = *(const float4*)&x[base0];
        float4 a1 = *(const float4*)&x[base1];
        float4 r0, r1;
        const float* p0 = (const float*)&a0;
        const float* p1 = (const float*)&a1;
        float* q0 = (float*)&r0;
        float* q1 = (float*)&r1;
        uint16_t h0[4], h1[4];
#pragma unroll
        for (int i = 0; i < 4; i++) {
            float v = p0[i] * 0.5f;
            float s0 = (v >= 1.0f) ? 1.0f : 0.0f;
            if (s0 != 0.0f) v = 0.0f;
            v = v + (p1[i] - v) * 0.5f;
            float s1 = (v >= 1.0f) ? 1.0f : 0.0f;
            q0[i] = s0;
            q1[i] = s1;
            h0[i] = (s0 != 0.0f) ? 0x3F80 : 0;   // bf16 1.0 / 0.0
            h1[i] = (s1 != 0.0f) ? 0x3F80 : 0;
        }
        *(float4*)&xs[base0] = r0;
        *(float4*)&xs[base1] = r1;
        // swizzled store: col = (tx*4) ^ (((cl>>3)&7)<<3), 4 halves via uint2
        int col = (tx * 4) ^ (((cl >> 3) & 7) << 3);
        uint2 w0 = make_uint2((uint32_t)h0[0] | ((uint32_t)h0[1] << 16),
                              (uint32_t)h0[2] | ((uint32_t)h0[3] << 16));
        uint2 w1 = make_uint2((uint32_t)h1[0] | ((uint32_t)h1[1] << 16),
                              (uint32_t)h1[2] | ((uint32_t)h1[3] << 16));
        *(uint2*)&st[0][cl][col] = w0;
        *(uint2*)&st[1][cl][col] = w1;
    }
    __syncthreads();
    __nv_bfloat16* xt = (__nv_bfloat16*)g_xt4;
#pragma unroll
    for (int it = 0; it < 4; ++it) {
        int u = tid + it * 256;            // 0..1023
        int t = u >> 9;
        int r = u & 511;
        int nl = r >> 3;
        int c8 = r & 7;
        int col = nl ^ (c8 << 3);
        uint32_t w[4];
#pragma unroll
        for (int jp = 0; jp < 4; ++jp) {
            uint32_t lo = st[t][c8 * 8 + jp * 2][col];
            uint32_t hi = st[t][c8 * 8 + jp * 2 + 1][col];
            w[jp] = lo | (hi << 16);
        }
        *(uint4*)&xt[((size_t)(t * B_ + b) * N_ + n0 + nl) * C_ + c0 + c8 * 8] =
            make_uint4(w[0], w[1], w[2], w[3]);
    }
}

// ---------------------------------------------------------------------------
// Kernel 2: HMMA GEMM for q/k/v + BN + LIF; fp32 spike outputs + bit-packed
// spikes. MODE 0: pack along channel (q). MODE 1: pack along n (k, v).
// 3-stage cp.async pipeline, one __syncthreads per K-chunk.
// ---------------------------------------------------------------------------
template <int MODE>
__global__ __launch_bounds__(256) void hmma_qkv(
    int widx, float* __restrict__ outp,
    const float* __restrict__ gamma, const float* __restrict__ beta,
    const float* __restrict__ mean, const float* __restrict__ var) {
    extern __shared__ __align__(16) char smem[];
    uint32_t sb = smem_u32(smem);
    const int tid = threadIdx.x;
    const int lane = tid & 31;
    const int wid = tid >> 5;
    const int wo = wid >> 2;
    const int wn = wid & 3;
    const int n0 = blockIdx.x * 128;
    const int o0 = blockIdx.y * 64;
    const int b  = blockIdx.z;

    const __nv_bfloat16* wh = (const __nv_bfloat16*)g_whi4 + widx * 65536 + o0 * C_;
    const __nv_bfloat16* wl = (const __nv_bfloat16*)g_wlo4 + widx * 65536 + o0 * C_;
    const __nv_bfloat16* xt = (const __nv_bfloat16*)g_xt4;
    const __nv_bfloat16* x0g = xt + ((size_t)b * N_ + n0) * C_;
    const __nv_bfloat16* x1g = xt + ((size_t)(B_ + b) * N_ + n0) * C_;

    float d[2][4][2][4];
#pragma unroll
    for (int a = 0; a < 2; a++)
#pragma unroll
        for (int c = 0; c < 4; c++)
#pragma unroll
            for (int t = 0; t < 2; t++)
#pragma unroll
                for (int j = 0; j < 4; j++) d[a][c][t][j] = 0.f;

    const int lr = tid >> 2;
    const int lj = tid & 3;
    auto load_chunk = [&](int c0, int stg) {
        uint32_t s0 = sb + (uint32_t)stg * SSTG;
        cp16(s0 + WH_OFF + lr * 80 + lj * 16, wh + (size_t)lr * C_ + c0 + lj * 8);
        cp16(s0 + WL_OFF + lr * 80 + lj * 16, wl + (size_t)lr * C_ + c0 + lj * 8);
        cp16(s0 + X0_OFF + lr * 80 + lj * 16, x0g + (size_t)lr * C_ + c0 + lj * 8);
        cp16(s0 + X0_OFF + (64 + lr) * 80 + lj * 16, x0g + (size_t)(64 + lr) * C_ + c0 + lj * 8);
        cp16(s0 + X1_OFF + lr * 80 + lj * 16, x1g + (size_t)lr * C_ + c0 + lj * 8);
        cp16(s0 + X1_OFF + (64 + lr) * 80 + lj * 16, x1g + (size_t)(64 + lr) * C_ + c0 + lj * 8);
    };

    load_chunk(0, 0);
    CP_COMMIT();
    load_chunk(32, 1);
    CP_COMMIT();

    const int arow = (lane & 7) + ((lane >> 3) & 1) * 8;
    const int acol = ((lane >> 4) & 1) * 16;
    const int brow = (lane & 7) + ((lane >> 4) & 1) * 8;
    const int bcol = ((lane >> 3) & 1) * 16;

#pragma unroll
    for (int ch = 0; ch < 8; ++ch) {
        if (ch < 7) { CP_WAIT1(); } else { CP_WAIT0(); }
        __syncthreads();
        if (ch + 2 < 8) {
            load_chunk((ch + 2) * 32, (ch + 2) % 3);
            CP_COMMIT();
        }
        uint32_t s0 = sb + (uint32_t)(ch % 3) * SSTG;
        uint32_t aW = s0 + WH_OFF + (wo * 32) * 80;
        uint32_t aX = s0 + X0_OFF + (wn * 32) * 80;
#pragma unroll
        for (int k16 = 0; k16 < 2; ++k16) {
            int kb = k16 * 32;
            uint32_t ah[2][4], al[2][4];
#pragma unroll
            for (int ot = 0; ot < 2; ++ot) {
                uint32_t ad = aW + (uint32_t)(ot * 16 + arow) * 80 + kb + acol;
                ldm4(ah[ot], ad);
                ldm4(al[ot], ad + (WL_OFF - WH_OFF));
            }
            uint32_t bf[2][4][2];
#pragma unroll
            for (int t = 0; t < 2; ++t) {
                uint32_t bbase = aX + (uint32_t)t * (X1_OFF - X0_OFF);
#pragma unroll
                for (int ns = 0; ns < 2; ++ns) {
                    uint32_t r[4];
                    ldm4(r, bbase + (uint32_t)(ns * 16 + brow) * 80 + kb + bcol);
                    bf[t][ns * 2][0] = r[0];
                    bf[t][ns * 2][1] = r[1];
                    bf[t][ns * 2 + 1][0] = r[2];
                    bf[t][ns * 2 + 1][1] = r[3];
                }
            }
#pragma unroll
            for (int t = 0; t < 2; ++t)
#pragma unroll
                for (int ot = 0; ot < 2; ++ot)
#pragma unroll
                    for (int nt = 0; nt < 4; ++nt) {
                        mma16816(d[ot][nt][t], ah[ot], bf[t][nt]);
                        mma16816(d[ot][nt][t], al[ot], bf[t][nt]);
                    }
        }
    }

    // Epilogue: BN + LIF, fp32 spike stores + bit packing
    const int la = lane & 3;
    const int g  = lane >> 2;
    const int obase = o0 + wo * 32 + g;
    const int nbase = n0 + wn * 32 + 2 * la;

    uint32_t pk[2][2][2];
    uint32_t pc[2][4][2];
#pragma unroll
    for (int t = 0; t < 2; ++t) {
#pragma unroll
        for (int i = 0; i < 2; ++i)
#pragma unroll
            for (int j = 0; j < 2; ++j) pk[t][i][j] = 0u;
#pragma unroll
        for (int i = 0; i < 4; ++i)
#pragma unroll
            for (int j = 0; j < 2; ++j) pc[t][i][j] = 0u;
    }

#pragma unroll
    for (int ot = 0; ot < 2; ++ot) {
#pragma unroll
        for (int rr = 0; rr < 2; ++rr) {
            int o = obase + ot * 16 + rr * 8;
            float gm = __ldg(&gamma[o]);
            float sq = sqrtf(__ldg(&var[o]) + 1e-5f);
            float inv = gm / sq;
            float sh  = __ldg(&beta[o]) - __ldg(&mean[o]) * gm / sq;
            size_t ro0 = ((size_t)b * C_ + o) * N_;
            size_t ro1 = ((size_t)(B_ + b) * C_ + o) * N_;
#pragma unroll
            for (int nt = 0; nt < 4; ++nt) {
                int n = nbase + nt * 8;
                float s0v[2], s1v[2];
#pragma unroll
                for (int cc = 0; cc < 2; ++cc) {
                    float y0 = d[ot][nt][0][rr * 2 + cc] * inv + sh;
                    float y1 = d[ot][nt][1][rr * 2 + cc] * inv + sh;
                    float v = y0 * 0.5f;
                    float sp0 = (v >= 1.0f) ? 1.0f : 0.0f;
                    if (sp0 != 0.0f) v = 0.0f;
                    v = v + (y1 - v) * 0.5f;
                    float sp1 = (v >= 1.0f) ? 1.0f : 0.0f;
                    s0v[cc] = sp0;
                    s1v[cc] = sp1;
                    if (MODE == 0) {
                        uint32_t bit = 1u << (g + rr * 8 + ot * 16);
                        if (sp0 != 0.0f) pc[0][nt][cc] |= bit;
                        if (sp1 != 0.0f) pc[1][nt][cc] |= bit;
                    } else {
                        uint32_t bit = 1u << (nt * 8 + la * 2 + cc);
                        if (sp0 != 0.0f) pk[0][ot][rr] |= bit;
                        if (sp1 != 0.0f) pk[1][ot][rr] |= bit;
                    }
                }
                *(float2*)&outp[ro0 + n] = make_float2(s0v[0], s0v[1]);
                *(float2*)&outp[ro1 + n] = make_float2(s1v[0], s1v[1]);
            }
        }
    }

    if (MODE == 0) {
        const int hword = (o0 + wo * 32) >> 5;
#pragma unroll
        for (int t = 0; t < 2; ++t)
#pragma unroll
            for (int nt = 0; nt < 4; ++nt)
#pragma unroll
                for (int cc = 0; cc < 2; ++cc) {
                    uint32_t w = pc[t][nt][cc];
                    w |= __shfl_xor_sync(0xffffffffu, w, 4);
                    w |= __shfl_xor_sync(0xffffffffu, w, 8);
                    w |= __shfl_xor_sync(0xffffffffu, w, 16);
                    if (g == 0) {
                        int n = nbase + nt * 8 + cc;
                        g_qpk[((size_t)(t * B_ + b) * N_ + n) * 8 + hword] = w;
                    }
                }
    } else {
        uint32_t* pko = (widx == 1) ? g_kpk : g_vpk;
        const int nw = (n0 + wn * 32) >> 5;
#pragma unroll
        for (int t = 0; t < 2; ++t)
#pragma unroll
            for (int ot = 0; ot < 2; ++ot)
#pragma unroll
                for (int rr = 0; rr < 2; ++rr) {
                    uint32_t w = pk[t][ot][rr];
                    w |= __shfl_xor_sync(0xffffffffu, w, 1);
                    w |= __shfl_xor_sync(0xffffffffu, w, 2);
                    if (la == 0) {
                        int o = obase + ot * 16 + rr * 8;
                        pko[((size_t)(t * B_ + b) * C_ + o) * 128 + nw] = w;
                    }
                }
    }
}

// ---------------------------------------------------------------------------
// Kernel 3: kv via popcount over packed bits
// ---------------------------------------------------------------------------
__global__ __launch_bounds__(256) void kv_pk_kernel() {
    int h = blockIdx.x, b = blockIdx.y, t = blockIdx.z;
    int tb = t * B_ + b;
    __shared__ uint32_t ks[32 * 129];
    __shared__ uint32_t vs[32 * 129];
    int tid = threadIdx.x;
    const uint32_t* kp = g_kpk + ((size_t)tb * C_ + h * D_) * 128;
    const uint32_t* vp = g_vpk + ((size_t)tb * C_ + h * D_) * 128;
    for (int i = tid; i < 4096; i += 256) {
        int dd = i >> 7, w = i & 127;
        ks[dd * 129 + w] = kp[i];
        vs[dd * 129 + w] = vp[i];
    }
    __syncthreads();
    float* kvout = g_kv + ((size_t)tb * NH_ + h) * (D_ * D_);
    for (int p = tid; p < 1024; p += 256) {
        int dd = p >> 5, e = p & 31;
        const uint32_t* kd = ks + dd * 129;
        const uint32_t* ve = vs + e * 129;
        int acc = 0;
#pragma unroll 8
        for (int w = 0; w < 128; ++w) acc += __popc(kd[w] & ve[w]);
        kvout[p] = (float)acc;
    }
}

// ---------------------------------------------------------------------------
// Kernel 4: attn via masked row-sum, LIF(0.5) -> g_st (bf16 [n,c])
// ---------------------------------------------------------------------------
__global__ __launch_bounds__(256) void attn_pk_kernel() {
    __shared__ float kvs[2][32][33];
    int n0 = blockIdx.x * 128;
    int h = blockIdx.y;
    int b = blockIdx.z;
    int tid = threadIdx.x;

    for (int l = tid; l < 2048; l += 256) {
        int t = l >> 10;
        int r = l & 1023;
        kvs[t][r >> 5][r & 31] = g_kv[((size_t)(t * B_ + b) * NH_ + h) * 1024 + r];
    }
    __syncthreads();

    int nl = tid >> 1;
    int eh = (tid & 1) * 16;
    int nn = n0 + nl;
    uint32_t qw0 = g_qpk[((size_t)b * N_ + nn) * 8 + h];
    uint32_t qw1 = g_qpk[((size_t)(B_ + b) * N_ + nn) * 8 + h];

    float a0[16], a1[16];
#pragma unroll
    for (int j = 0; j < 16; ++j) { a0[j] = 0.f; a1[j] = 0.f; }
#pragma unroll 4
    for (int dd = 0; dd < 32; ++dd) {
        if ((qw0 >> dd) & 1) {
#pragma unroll
            for (int j = 0; j < 16; ++j) a0[j] += kvs[0][dd][eh + j];
        }
        if ((qw1 >> dd) & 1) {
#pragma unroll
            for (int j = 0; j < 16; ++j) a1[j] += kvs[1][dd][eh + j];
        }
    }

    __nv_bfloat16 o0[16], o1[16];
#pragma unroll
    for (int j = 0; j < 16; ++j) {
        float y0 = a0[j] * 0.125f;
        float y1 = a1[j] * 0.125f;
        float v = y0 * 0.5f;
        float t0 = (v >= 0.5f) ? 1.0f : 0.0f;
        if (t0 != 0.0f) v = 0.0f;
        v = v + (y1 - v) * 0.5f;
        float t1 = (v >= 0.5f) ? 1.0f : 0.0f;
        o0[j] = __float2bfloat16(t0);
        o1[j] = __float2bfloat16(t1);
    }
    __nv_bfloat16* stt = (__nv_bfloat16*)g_st4;
    size_t b0 = ((size_t)b * N_ + nn) * C_ + h * D_ + eh;
    size_t b1 = ((size_t)(B_ + b) * N_ + nn) * C_ + h * D_ + eh;
    *(uint4*)&stt[b0] = *(uint4*)&o0[0];
    *(uint4*)&stt[b0 + 8] = *(uint4*)&o0[8];
    *(uint4*)&stt[b1] = *(uint4*)&o1[0];
    *(uint4*)&stt[b1 + 8] = *(uint4*)&o1[8];
}

// ---------------------------------------------------------------------------
// Kernel 5: HMMA projection GEMM: out = BN(Wp @ s + bp). 3-stage pipeline.
// ---------------------------------------------------------------------------
__global__ __launch_bounds__(256) void hmma_p(
    float* __restrict__ outp, const float* __restrict__ bp,
    const float* __restrict__ gamma, const float* __restrict__ beta,
    const float* __restrict__ mean, const float* __restrict__ var) {
    extern __shared__ __align__(16) char smem[];
    uint32_t sb = smem_u32(smem);
    const int tid = threadIdx.x;
    const int lane = tid & 31;
    const int wid = tid >> 5;
    const int wo = wid >> 2;
    const int wn = wid & 3;
    const int n0 = blockIdx.x * 128;
    const int o0 = blockIdx.y * 64;
    const int z  = blockIdx.z;

    const __nv_bfloat16* wh = (const __nv_bfloat16*)g_whi4 + 3 * 65536 + o0 * C_;
    const __nv_bfloat16* wl = (const __nv_bfloat16*)g_wlo4 + 3 * 65536 + o0 * C_;
    const __nv_bfloat16* xg = (const __nv_bfloat16*)g_st4 + ((size_t)z * N_ + n0) * C_;

    float d[2][4][4];
#pragma unroll
    for (int a = 0; a < 2; a++)
#pragma unroll
        for (int c = 0; c < 4; c++)
#pragma unroll
            for (int j = 0; j < 4; j++) d[a][c][j] = 0.f;

    const int lr = tid >> 2;
    const int lj = tid & 3;
    auto load_chunk = [&](int c0, int stg) {
        uint32_t s0 = sb + (uint32_t)stg * SSTG_P;
        cp16(s0 + WH_OFF + lr * 80 + lj * 16, wh + (size_t)lr * C_ + c0 + lj * 8);
        cp16(s0 + WL_OFF + lr * 80 + lj * 16, wl + (size_t)lr * C_ + c0 + lj * 8);
        cp16(s0 + X0_OFF + lr * 80 + lj * 16, xg + (size_t)lr * C_ + c0 + lj * 8);
        cp16(s0 + X0_OFF + (64 + lr) * 80 + lj * 16, xg + (size_t)(64 + lr) * C_ + c0 + lj * 8);
    };

    load_chunk(0, 0);
    CP_COMMIT();
    load_chunk(32, 1);
    CP_COMMIT();

    const int arow = (lane & 7) + ((lane >> 3) & 1) * 8;
    const int acol = ((lane >> 4) & 1) * 16;
    const int brow = (lane & 7) + ((lane >> 4) & 1) * 8;
    const int bcol = ((lane >> 3) & 1) * 16;

#pragma unroll
    for (int ch = 0; ch < 8; ++ch) {
        if (ch < 7) { CP_WAIT1(); } else { CP_WAIT0(); }
        __syncthreads();
        if (ch + 2 < 8) {
            load_chunk((ch + 2) * 32, (ch + 2) % 3);
            CP_COMMIT();
        }
        uint32_t s0 = sb + (uint32_t)(ch % 3) * SSTG_P;
        uint32_t aW = s0 + WH_OFF + (wo * 32) * 80;
        uint32_t aX = s0 + X0_OFF + (wn * 32) * 80;
#pragma unroll
        for (int k16 = 0; k16 < 2; ++k16) {
            int kb = k16 * 32;
            uint32_t ah[2][4], al[2][4];
#pragma unroll
            for (int ot = 0; ot < 2; ++ot) {
                uint32_t ad = aW + (uint32_t)(ot * 16 + arow) * 80 + kb + acol;
                ldm4(ah[ot], ad);
                ldm4(al[ot], ad + (WL_OFF - WH_OFF));
            }
            uint32_t bf[4][2];
#pragma unroll
            for (int ns = 0; ns < 2; ++ns) {
                uint32_t r[4];
                ldm4(r, aX + (uint32_t)(ns * 16 + brow) * 80 + kb + bcol);
                bf[ns * 2][0] = r[0];
                bf[ns * 2][1] = r[1];
                bf[ns * 2 + 1][0] = r[2];
                bf[ns * 2 + 1][1] = r[3];
            }
#pragma unroll
            for (int ot = 0; ot < 2; ++ot)
#pragma unroll
                for (int nt = 0; nt < 4; ++nt) {
                    mma16816(d[ot][nt], ah[ot], bf[nt]);
                    mma16816(d[ot][nt], al[ot], bf[nt]);
                }
        }
    }

    const int obase = o0 + wo * 32 + (lane >> 2);
    const int nbase = n0 + wn * 32 + 2 * (lane & 3);
#pragma unroll
    for (int ot = 0; ot < 2; ++ot) {
#pragma unroll
        for (int rr = 0; rr < 2; ++rr) {
            int o = obase + ot * 16 + rr * 8;
            float g  = __ldg(&gamma[o]);
            float sq = sqrtf(__ldg(&var[o]) + 1e-5f);
            float inv = g / sq;
            float sh  = __ldg(&beta[o]) - __ldg(&mean[o]) * g / sq;
            float bb  = __ldg(&bp[o]);
            size_t ro = ((size_t)z * C_ + o) * N_;
#pragma unroll
            for (int nt = 0; nt < 4; ++nt) {
                int n = nbase + nt * 8;
                float y0 = (d[ot][nt][rr * 2 + 0] + bb) * inv + sh;
                float y1 = (d[ot][nt][rr * 2 + 1] + bb) * inv + sh;
                *(float2*)&outp[ro + n] = make_float2(y0, y1);
            }
        }
    }
}

// ---------------------------------------------------------------------------
extern "C" void kernel_launch(void* const* d_in, const int* in_sizes, int n_in,
                              void* d_out, int out_size) {
    const float* x  = (const float*)d_in[0];
    const float* wq = (const float*)d_in[1];
    const float* wk = (const float*)d_in[2];
    const float* wv = (const float*)d_in[3];
    const float* wp = (const float*)d_in[4];
    const float* bp = (const float*)d_in[5];
    const float* qg = (const float*)d_in[6];
    const float* qb = (const float*)d_in[7];
    const float* qm = (const float*)d_in[8];
    const float* qv = (const float*)d_in[9];
    const float* kg = (const float*)d_in[10];
    const float* kb = (const float*)d_in[11];
    const float* km = (const float*)d_in[12];
    const float* kv_ = (const float*)d_in[13];
    const float* vg = (const float*)d_in[14];
    const float* vb = (const float*)d_in[15];
    const float* vm = (const float*)d_in[16];
    const float* vv = (const float*)d_in[17];
    const float* pg = (const float*)d_in[18];
    const float* pb = (const float*)d_in[19];
    const float* pm = (const float*)d_in[20];
    const float* pv = (const float*)d_in[21];

    float* out = (float*)d_out;
    float* xs = out + (size_t)SZ;
    float* qo = out + 2 * (size_t)SZ;
    float* ko = out + 3 * (size_t)SZ;
    float* vo = out + 4 * (size_t)SZ;

    cudaFuncSetAttribute(hmma_qkv<0>, cudaFuncAttributeMaxDynamicSharedMemorySize, 3 * SSTG);
    cudaFuncSetAttribute(hmma_qkv<1>, cudaFuncAttributeMaxDynamicSharedMemorySize, 3 * SSTG);
    cudaFuncSetAttribute(hmma_p, cudaFuncAttributeMaxDynamicSharedMemorySize, 3 * SSTG_P);

    // 0) weight split
    split_w_kernel<<<1024, 256>>>(wq, wk, wv, wp);

    // 1) input LIF -> xs (fp32) + transposed bf16 activations
    lif_x_t_kernel<<<dim3(N_ / 64, C_ / 64, B_), 256>>>(x, xs);

    // 2) q/k/v HMMA GEMM + BN + LIF (+ bit packing)
    dim3 gg(N_ / 128, C_ / 64, B_);
    hmma_qkv<0><<<gg, 256, 3 * SSTG>>>(0, qo, qg, qb, qm, qv);
    hmma_qkv<1><<<gg, 256, 3 * SSTG>>>(1, ko, kg, kb, km, kv_);
    hmma_qkv<1><<<gg, 256, 3 * SSTG>>>(2, vo, vg, vb, vm, vv);

    // 3) kv via popcount
    kv_pk_kernel<<<dim3(NH_, B_, T_), 256>>>();

    // 4) attn via masked row-sum + LIF(0.5) -> bf16 spikes
    attn_pk_kernel<<<dim3(N_ / 128, NH_, B_), 256>>>();

    // 5) projection HMMA GEMM + bias + BN -> out
    hmma_p<<<dim3(N_ / 128, C_ / 64, T_ * B_), 256, 3 * SSTG_P>>>(
        out, bp, pg, pb, pm, pv);
}